// round 12
// baseline (speedup 1.0000x reference)
#include <cuda_runtime.h>
#include <cuda_fp16.h>
#include <math.h>

// Fixed problem shape (per reference setup_inputs)
#define NN 50000
#define FF 128
#define H1 8
#define C1 8
#define HC1 64
#define EMAX 900000   // E (800000) + N (50000) self loops
#define NB  592       // CSR blocks: 148 SMs x 4 co-resident blocks

// ---------------- device scratch (no allocation allowed) ----------------
__device__ __align__(16) __half g_h1[NN * HC1];  // layer1 features (fp16)
__device__ __align__(16) float  g_x2[NN * HC1];  // ELU(layer1 out) fp32
__device__ __align__(16) __half g_h2[NN * FF];   // layer2 features (fp16)
__device__ float g_as1[NN * H1];
__device__ float g_ad1[NN * H1];
__device__ float g_as2[NN];
__device__ float g_ad2[NN];
__device__ int   g_rowptr[NN + 1];
__device__ int   g_cnt[NN];
__device__ int   g_col[EMAX];                    // src ids grouped by dst
__device__ int   g_bsum[NB];
__device__ unsigned g_bar;                       // monotonic grid-barrier ticket

// ---------------- helpers ----------------
__device__ __forceinline__ float leaky(float x) { return x > 0.0f ? x : 0.2f * x; }

__device__ __forceinline__ void fma2(unsigned long long& d, unsigned long long a,
                                     unsigned long long b, unsigned long long c) {
    asm("fma.rn.f32x2 %0, %1, %2, %3;" : "=l"(d) : "l"(a), "l"(b), "l"(c));
}
__device__ __forceinline__ unsigned long long dup2(float x) {
    unsigned long long d;
    unsigned int u = __float_as_uint(x);
    asm("mov.b64 %0, {%1, %2};" : "=l"(d) : "r"(u), "r"(u));
    return d;
}
__device__ __forceinline__ void unpack2(unsigned long long v, float& lo, float& hi) {
    unsigned int a, b;
    asm("mov.b64 {%0, %1}, %2;" : "=r"(a), "=r"(b) : "l"(v));
    lo = __uint_as_float(a);
    hi = __uint_as_float(b);
}

// grid barrier: monotonic ticket counter (no reset across graph replays).
// Requires all NB blocks co-resident (enforced via __launch_bounds__ min-blocks).
__device__ __forceinline__ void gridbar() {
    __syncthreads();
    if (threadIdx.x == 0) {
        __threadfence();
        unsigned ticket = atomicAdd(&g_bar, 1u);
        unsigned target = (ticket / NB + 1u) * NB;
        while (*((volatile unsigned*)&g_bar) < target) __nanosleep(64);
    }
    __syncthreads();
    __threadfence();
}

// ---------------- merged CSR build: one kernel, 4 grid barriers ----------
// phases: zero+detect | hist | block sums | prefix+scan+rowptr | scatter
__global__ void __launch_bounds__(256, 4) k_csr(const void* __restrict__ ei,
                                                int E, int Etot, int N, int chunk) {
    __shared__ int sscan[256];
    int t = threadIdx.x, b = blockIdx.x;
    const int nth = NB * 256;
    int gtid = b * 256 + t;

    // P0: zero counts; probe dtype (int64 <50000 -> odd 32-bit words zero)
    for (int i = gtid; i < N; i += nth) g_cnt[i] = 0;
    int is64 = 1;
    {
        const int* p = (const int*)ei;
#pragma unroll
        for (int k = 0; k < 8; k++)
            if (p[2 * k + 1] != 0) is64 = 0;
    }
    gridbar();

    // P1: histogram of dst
    for (int e = gtid; e < Etot; e += nth) {
        int dst;
        if (e < E) dst = is64 ? (int)((const long long*)ei)[E + e]
                              : ((const int*)ei)[E + e];
        else       dst = e - E;
        atomicAdd(&g_cnt[dst], 1);
    }
    gridbar();

    // P2: per-block chunk sums (chunk <= 512; thread handles pair 2t, 2t+1)
    int cb = b * chunk;
    int i0 = cb + 2 * t, i1 = i0 + 1;
    int v0 = (2 * t < chunk && i0 < N) ? g_cnt[i0] : 0;
    int v1 = (2 * t + 1 < chunk && i1 < N) ? g_cnt[i1] : 0;
    int st = v0 + v1;
    sscan[t] = st;
    __syncthreads();
#pragma unroll
    for (int off = 128; off > 0; off >>= 1) {
        if (t < off) sscan[t] += sscan[t + off];
        __syncthreads();
    }
    if (t == 0) g_bsum[b] = sscan[0];
    gridbar();

    // P3: block offset (strided prefix over NB block sums) + local scan
    int partial = 0;
    for (int j = t; j < b; j += 256) partial += g_bsum[j];
    __syncthreads();
    sscan[t] = partial;
    __syncthreads();
#pragma unroll
    for (int off = 128; off > 0; off >>= 1) {
        if (t < off) sscan[t] += sscan[t + off];
        __syncthreads();
    }
    int boff = sscan[0];
    __syncthreads();
    sscan[t] = st;
    __syncthreads();
#pragma unroll
    for (int off = 1; off < 256; off <<= 1) {
        int u = (t >= off) ? sscan[t - off] : 0;
        __syncthreads();
        sscan[t] += u;
        __syncthreads();
    }
    int excl = sscan[t] - st + boff;
    if (2 * t < chunk && i0 < N)     { g_rowptr[i0] = excl;      g_cnt[i0] = 0; }
    if (2 * t + 1 < chunk && i1 < N) { g_rowptr[i1] = excl + v0; g_cnt[i1] = 0; }
    if (gtid == 0) g_rowptr[N] = Etot;
    gridbar();

    // P4: scatter src grouped by dst
    for (int e = gtid; e < Etot; e += nth) {
        int src, dst;
        if (e < E) {
            if (is64) {
                const long long* p = (const long long*)ei;
                src = (int)p[e]; dst = (int)p[E + e];
            } else {
                const int* p = (const int*)ei;
                src = p[e]; dst = p[E + e];
            }
        } else src = dst = e - E;
        int pos = g_rowptr[dst] + atomicAdd(&g_cnt[dst], 1);
        g_col[pos] = src;
    }
}

// ---------------- layer1 GEMM + fused logits ------------------------------
// 128 nodes/block, K split into 2 halves of 64 (smem stays 48KB).
__global__ void __launch_bounds__(256) k_gemm1(const float* __restrict__ x,
                                               const float* __restrict__ W1,
                                               const float* __restrict__ att_s,
                                               const float* __restrict__ att_d,
                                               int N) {
    __shared__ float ws[64 * HC1];       // 16KB [k][c], half-K
    __shared__ float xs[64 * 128];       // 32KB [k][n], half-K, 128 nodes
    int tid = threadIdx.x;
    int nbase = blockIdx.x * 128;
    int cg = tid & 15, ng = tid >> 4;
    int c0 = cg * 4, n0 = ng * 8;
    unsigned long long acc[8][2] = {};

    for (int half = 0; half < 2; half++) {
        {
            const float4* W4 = (const float4*)(W1 + half * 64 * HC1);
            float4* ws4 = (float4*)ws;
            for (int i = tid; i < 64 * HC1 / 4; i += 256) ws4[i] = W4[i];
        }
        for (int i = tid; i < 128 * 16; i += 256) {
            int n = i & 127, k4 = i >> 7;
            int gn = nbase + n;
            float4 v = (gn < N)
                ? ((const float4*)x)[(size_t)gn * 32 + half * 16 + k4]
                : make_float4(0.f, 0.f, 0.f, 0.f);
            xs[(k4 * 4 + 0) * 128 + n] = v.x;
            xs[(k4 * 4 + 1) * 128 + n] = v.y;
            xs[(k4 * 4 + 2) * 128 + n] = v.z;
            xs[(k4 * 4 + 3) * 128 + n] = v.w;
        }
        __syncthreads();
#pragma unroll 16
        for (int k = 0; k < 64; k++) {
            ulonglong2 wv = ((const ulonglong2*)(ws + k * HC1))[cg];
            float4 xa = ((const float4*)(xs + k * 128))[ng * 2];
            float4 xb = ((const float4*)(xs + k * 128))[ng * 2 + 1];
            unsigned long long xd[8];
            xd[0] = dup2(xa.x); xd[1] = dup2(xa.y); xd[2] = dup2(xa.z); xd[3] = dup2(xa.w);
            xd[4] = dup2(xb.x); xd[5] = dup2(xb.y); xd[6] = dup2(xb.z); xd[7] = dup2(xb.w);
#pragma unroll
            for (int i = 0; i < 8; i++) {
                fma2(acc[i][0], xd[i], wv.x, acc[i][0]);
                fma2(acc[i][1], xd[i], wv.y, acc[i][1]);
            }
        }
        __syncthreads();
    }

    float sa0 = att_s[c0], sa1 = att_s[c0+1], sa2 = att_s[c0+2], sa3 = att_s[c0+3];
    float da0 = att_d[c0], da1 = att_d[c0+1], da2 = att_d[c0+2], da3 = att_d[c0+3];
    int head = cg >> 1;
#pragma unroll
    for (int i = 0; i < 8; i++) {
        float a0, a1, a2, a3;
        unpack2(acc[i][0], a0, a1);
        unpack2(acc[i][1], a2, a3);
        int gn = nbase + n0 + i;
        if (gn < N) {
            *((__half2*)&g_h1[gn * HC1 + c0])     = __floats2half2_rn(a0, a1);
            *((__half2*)&g_h1[gn * HC1 + c0 + 2]) = __floats2half2_rn(a2, a3);
        }
        float s = a0*sa0 + a1*sa1 + a2*sa2 + a3*sa3;
        float d = a0*da0 + a1*da1 + a2*da2 + a3*da3;
        s += __shfl_xor_sync(0xFFFFFFFF, s, 1);
        d += __shfl_xor_sync(0xFFFFFFFF, d, 1);
        if ((cg & 1) == 0 && gn < N) {
            g_as1[gn * H1 + head] = s;
            g_ad1[gn * H1 + head] = d;
        }
    }
}

// ---------------- layer1 aggregate: warp/dst, 4x pipelined ----------------
__global__ void k_agg1(const float* __restrict__ b1, int N) {
    int w = (blockIdx.x * blockDim.x + threadIdx.x) >> 5;
    if (w >= N) return;
    int lane = threadIdx.x & 31;
    int head = lane >> 2, q = lane & 3;
    int r0 = g_rowptr[w], r1 = g_rowptr[w + 1];
    float adv = g_ad1[w * H1 + head];
    float s = 0.f, a0 = 0.f, a1 = 0.f;
    int i = r0;
    for (; i + 4 <= r1; i += 4) {
        int s0 = g_col[i], s1 = g_col[i+1], s2 = g_col[i+2], s3 = g_col[i+3];
        float l0 = g_as1[s0 * H1 + head];
        float l1 = g_as1[s1 * H1 + head];
        float l2 = g_as1[s2 * H1 + head];
        float l3 = g_as1[s3 * H1 + head];
        __half2 p0 = *(const __half2*)&g_h1[s0 * HC1 + head * C1 + q * 2];
        __half2 p1 = *(const __half2*)&g_h1[s1 * HC1 + head * C1 + q * 2];
        __half2 p2 = *(const __half2*)&g_h1[s2 * HC1 + head * C1 + q * 2];
        __half2 p3 = *(const __half2*)&g_h1[s3 * HC1 + head * C1 + q * 2];
        float e0 = __expf(leaky(l0 + adv));
        float e1 = __expf(leaky(l1 + adv));
        float e2 = __expf(leaky(l2 + adv));
        float e3 = __expf(leaky(l3 + adv));
        s += (e0 + e1) + (e2 + e3);
        float2 h0 = __half22float2(p0), h1v = __half22float2(p1);
        float2 h2v = __half22float2(p2), h3 = __half22float2(p3);
        a0 = fmaf(e0, h0.x, a0);  a1 = fmaf(e0, h0.y, a1);
        a0 = fmaf(e1, h1v.x, a0); a1 = fmaf(e1, h1v.y, a1);
        a0 = fmaf(e2, h2v.x, a0); a1 = fmaf(e2, h2v.y, a1);
        a0 = fmaf(e3, h3.x, a0);  a1 = fmaf(e3, h3.y, a1);
    }
    for (; i < r1; i++) {
        int src = g_col[i];
        float ex = __expf(leaky(g_as1[src * H1 + head] + adv));
        s += ex;
        float2 hv = __half22float2(*(const __half2*)&g_h1[src * HC1 + head * C1 + q * 2]);
        a0 = fmaf(ex, hv.x, a0);
        a1 = fmaf(ex, hv.y, a1);
    }
    s = (s > 0.f) ? s : 1.f;
    int j = head * C1 + q * 2;
    float v0 = a0 / s + b1[j];
    float v1 = a1 / s + b1[j + 1];
    float2 r;
    r.x = v0 > 0.f ? v0 : expm1f(v0);
    r.y = v1 > 0.f ? v1 : expm1f(v1);
    *(float2*)&g_x2[w * HC1 + j] = r;
}

// ---------------- layer2 GEMM + fused logits (f32x2), fp16 h2 out ---------
__global__ void __launch_bounds__(256) k_gemm2(const float* __restrict__ W2,
                                               const float* __restrict__ att_s,
                                               const float* __restrict__ att_d,
                                               int N) {
    __shared__ float ws[HC1 * FF];       // 32KB [k][c]
    __shared__ float xs[HC1 * 64];       // 16KB [k][n] transposed
    int tid = threadIdx.x;
    int nbase = blockIdx.x * 64;
    const float4* W4 = (const float4*)W2;
    float4* ws4 = (float4*)ws;
    for (int i = tid; i < HC1 * FF / 4; i += 256) ws4[i] = W4[i];
    for (int i = tid; i < 64 * 16; i += 256) {
        int n = i & 63, k4 = i >> 6;
        int gn = nbase + n;
        float4 v = (gn < N) ? ((const float4*)g_x2)[(size_t)gn * 16 + k4]
                            : make_float4(0.f, 0.f, 0.f, 0.f);
        xs[(k4 * 4 + 0) * 64 + n] = v.x;
        xs[(k4 * 4 + 1) * 64 + n] = v.y;
        xs[(k4 * 4 + 2) * 64 + n] = v.z;
        xs[(k4 * 4 + 3) * 64 + n] = v.w;
    }
    __syncthreads();
    int cg = tid & 31, ng = tid >> 5;
    int c0 = cg * 4, n0 = ng * 8;
    unsigned long long acc[8][2] = {};
#pragma unroll 16
    for (int k = 0; k < HC1; k++) {
        ulonglong2 wv = ((const ulonglong2*)(ws + k * FF))[cg];
        float4 xa = ((const float4*)(xs + k * 64))[ng * 2];
        float4 xb = ((const float4*)(xs + k * 64))[ng * 2 + 1];
        unsigned long long xd[8];
        xd[0] = dup2(xa.x); xd[1] = dup2(xa.y); xd[2] = dup2(xa.z); xd[3] = dup2(xa.w);
        xd[4] = dup2(xb.x); xd[5] = dup2(xb.y); xd[6] = dup2(xb.z); xd[7] = dup2(xb.w);
#pragma unroll
        for (int i = 0; i < 8; i++) {
            fma2(acc[i][0], xd[i], wv.x, acc[i][0]);
            fma2(acc[i][1], xd[i], wv.y, acc[i][1]);
        }
    }
    float4 sa = ((const float4*)att_s)[cg];
    float4 da = ((const float4*)att_d)[cg];
#pragma unroll
    for (int i = 0; i < 8; i++) {
        float a0, a1, a2, a3;
        unpack2(acc[i][0], a0, a1);
        unpack2(acc[i][1], a2, a3);
        int gn = nbase + n0 + i;
        if (gn < N) {
            *((__half2*)&g_h2[gn * FF + c0])     = __floats2half2_rn(a0, a1);
            *((__half2*)&g_h2[gn * FF + c0 + 2]) = __floats2half2_rn(a2, a3);
        }
        float s = a0*sa.x + a1*sa.y + a2*sa.z + a3*sa.w;
        float d = a0*da.x + a1*da.y + a2*da.z + a3*da.w;
#pragma unroll
        for (int off = 16; off > 0; off >>= 1) {
            s += __shfl_xor_sync(0xFFFFFFFF, s, off);
            d += __shfl_xor_sync(0xFFFFFFFF, d, off);
        }
        if (cg == 0 && gn < N) {
            g_as2[gn] = s;
            g_ad2[gn] = d;
        }
    }
}

// ---------------- layer2 aggregate: warp/dst, 4x pipelined ----------------
__global__ void k_agg2(float* __restrict__ out, const float* __restrict__ b2, int N) {
    int w = (blockIdx.x * blockDim.x + threadIdx.x) >> 5;
    if (w >= N) return;
    int lane = threadIdx.x & 31;
    int r0 = g_rowptr[w], r1 = g_rowptr[w + 1];
    float adv = g_ad2[w];
    float s = 0.f;
    float4 acc = make_float4(0.f, 0.f, 0.f, 0.f);
    int i = r0;
    for (; i + 4 <= r1; i += 4) {
        int s0 = g_col[i], s1 = g_col[i+1], s2 = g_col[i+2], s3 = g_col[i+3];
        float l0 = g_as2[s0], l1 = g_as2[s1], l2 = g_as2[s2], l3 = g_as2[s3];
        uint2 w0 = ((const uint2*)&g_h2[s0 * FF])[lane];
        uint2 w1 = ((const uint2*)&g_h2[s1 * FF])[lane];
        uint2 w2 = ((const uint2*)&g_h2[s2 * FF])[lane];
        uint2 w3 = ((const uint2*)&g_h2[s3 * FF])[lane];
        float e0 = __expf(leaky(l0 + adv));
        float e1 = __expf(leaky(l1 + adv));
        float e2 = __expf(leaky(l2 + adv));
        float e3 = __expf(leaky(l3 + adv));
        s += (e0 + e1) + (e2 + e3);
        float2 a01, a23;
        a01 = __half22float2(*(const __half2*)&w0.x);
        a23 = __half22float2(*(const __half2*)&w0.y);
        acc.x = fmaf(e0, a01.x, acc.x); acc.y = fmaf(e0, a01.y, acc.y);
        acc.z = fmaf(e0, a23.x, acc.z); acc.w = fmaf(e0, a23.y, acc.w);
        a01 = __half22float2(*(const __half2*)&w1.x);
        a23 = __half22float2(*(const __half2*)&w1.y);
        acc.x = fmaf(e1, a01.x, acc.x); acc.y = fmaf(e1, a01.y, acc.y);
        acc.z = fmaf(e1, a23.x, acc.z); acc.w = fmaf(e1, a23.y, acc.w);
        a01 = __half22float2(*(const __half2*)&w2.x);
        a23 = __half22float2(*(const __half2*)&w2.y);
        acc.x = fmaf(e2, a01.x, acc.x); acc.y = fmaf(e2, a01.y, acc.y);
        acc.z = fmaf(e2, a23.x, acc.z); acc.w = fmaf(e2, a23.y, acc.w);
        a01 = __half22float2(*(const __half2*)&w3.x);
        a23 = __half22float2(*(const __half2*)&w3.y);
        acc.x = fmaf(e3, a01.x, acc.x); acc.y = fmaf(e3, a01.y, acc.y);
        acc.z = fmaf(e3, a23.x, acc.z); acc.w = fmaf(e3, a23.y, acc.w);
    }
    for (; i < r1; i++) {
        int src = g_col[i];
        float ex = __expf(leaky(g_as2[src] + adv));
        s += ex;
        uint2 raw = ((const uint2*)&g_h2[src * FF])[lane];
        float2 h01 = __half22float2(*(const __half2*)&raw.x);
        float2 h23 = __half22float2(*(const __half2*)&raw.y);
        acc.x = fmaf(ex, h01.x, acc.x);
        acc.y = fmaf(ex, h01.y, acc.y);
        acc.z = fmaf(ex, h23.x, acc.z);
        acc.w = fmaf(ex, h23.y, acc.w);
    }
    s = (s > 0.f) ? s : 1.f;
    float4 bv = ((const float4*)b2)[lane];
    float4 r;
    r.x = acc.x / s + bv.x;
    r.y = acc.y / s + bv.y;
    r.z = acc.z / s + bv.z;
    r.w = acc.w / s + bv.w;
    ((float4*)&out[w * FF])[lane] = r;
}

// ---------------- launcher: 5 launches, single stream --------------------
extern "C" void kernel_launch(void* const* d_in, const int* in_sizes, int n_in,
                              void* d_out, int out_size) {
    const float* x   = (const float*)d_in[0];
    const void*  ei  = d_in[1];
    const float* W1  = (const float*)d_in[2];
    const float* as1 = (const float*)d_in[3];
    const float* ad1 = (const float*)d_in[4];
    const float* b1  = (const float*)d_in[5];
    const float* W2  = (const float*)d_in[6];
    const float* as2 = (const float*)d_in[7];
    const float* ad2 = (const float*)d_in[8];
    const float* b2  = (const float*)d_in[9];
    float*       out = (float*)d_out;

    int N     = in_sizes[0] / FF;     // 50000
    int E     = in_sizes[1] / 2;      // 800000
    int Etot  = E + N;
    int chunk = (N + NB - 1) / NB;    // 85 (<=512 required)

    k_csr<<<NB, 256>>>(ei, E, Etot, N, chunk);
    k_gemm1<<<(N + 127) / 128, 256>>>(x, W1, as1, ad1, N);
    k_agg1<<<(N * 32 + 255) / 256, 256>>>(b1, N);
    k_gemm2<<<(N + 63) / 64, 256>>>(W2, as2, ad2, N);
    k_agg2<<<(N * 32 + 255) / 256, 256>>>(out, b2, N);
}

// round 13
// speedup vs baseline: 1.0781x; 1.0781x over previous
#include <cuda_runtime.h>
#include <cuda_fp16.h>
#include <math.h>

// Fixed problem shape (per reference setup_inputs)
#define NN 50000
#define FF 128
#define H1 8
#define C1 8
#define HC1 64
#define EMAX 900000   // E (800000) + N (50000) self loops

// ---------------- device scratch (no allocation allowed) ----------------
__device__ __align__(16) __half g_h1[NN * HC1];  // layer1 features (fp16)
__device__ __align__(16) float  g_x2[NN * HC1];  // ELU(layer1 out) fp32
__device__ __align__(16) __half g_h2[NN * FF];   // layer2 features (fp16)
__device__ float g_as1[NN * H1];
__device__ float g_ad1[NN * H1];
__device__ float g_as2[NN];
__device__ float g_ad2[NN];
__device__ int   g_rowptr[NN + 1];
__device__ int   g_cnt[NN];
__device__ int   g_col[EMAX];                    // src ids grouped by dst
__device__ int   g_bsum[256];
__device__ int   g_is64;

// ---------------- helpers ----------------
__device__ __forceinline__ float leaky(float x) { return x > 0.0f ? x : 0.2f * x; }

__device__ __forceinline__ void fma2(unsigned long long& d, unsigned long long a,
                                     unsigned long long b, unsigned long long c) {
    asm("fma.rn.f32x2 %0, %1, %2, %3;" : "=l"(d) : "l"(a), "l"(b), "l"(c));
}
__device__ __forceinline__ unsigned long long dup2(float x) {
    unsigned long long d;
    unsigned int u = __float_as_uint(x);
    asm("mov.b64 %0, {%1, %2};" : "=l"(d) : "r"(u), "r"(u));
    return d;
}
__device__ __forceinline__ void unpack2(unsigned long long v, float& lo, float& hi) {
    unsigned int a, b;
    asm("mov.b64 {%0, %1}, %2;" : "=r"(a), "=r"(b) : "l"(v));
    lo = __uint_as_float(a);
    hi = __uint_as_float(b);
}

__device__ __forceinline__ void load_edge(const void* ei, int E, int e,
                                          int& src, int& dst) {
    if (g_is64) {
        const long long* p = (const long long*)ei;
        src = (int)p[e]; dst = (int)p[E + e];
    } else {
        const int* p = (const int*)ei;
        src = p[e]; dst = p[E + e];
    }
}
__device__ __forceinline__ int load_dst(const void* ei, int E, int e) {
    if (g_is64) return (int)((const long long*)ei)[E + e];
    return ((const int*)ei)[E + e];
}

// ---------------- zero counts + dtype probe (fused) ----------------------
__global__ void k_zero_detect(const int* __restrict__ ei32, int N) {
    int i = blockIdx.x * blockDim.x + threadIdx.x;
    if (i < N) g_cnt[i] = 0;
    if (blockIdx.x == 0 && threadIdx.x == 0) {
        int is64 = 1;
#pragma unroll
        for (int k = 0; k < 8; k++)
            if (ei32[2 * k + 1] != 0) is64 = 0;
        g_is64 = is64;
    }
}

__global__ void k_hist(const void* __restrict__ ei, int E, int Etot) {
    int e = blockIdx.x * blockDim.x + threadIdx.x;
    if (e >= Etot) return;
    int dst = (e < E) ? load_dst(ei, E, e) : e - E;
    atomicAdd(&g_cnt[dst], 1);
}

__global__ void k_bsum(int N) {
    __shared__ int red[256];
    int i = blockIdx.x * 256 + threadIdx.x;
    red[threadIdx.x] = (i < N) ? g_cnt[i] : 0;
    __syncthreads();
#pragma unroll
    for (int off = 128; off > 0; off >>= 1) {
        if (threadIdx.x < off) red[threadIdx.x] += red[threadIdx.x + off];
        __syncthreads();
    }
    if (threadIdx.x == 0) g_bsum[blockIdx.x] = red[0];
}

// per-block local scan; each block reduces its own bsum prefix (nb <= 256)
__global__ void k_scan2(int N, int Etot) {
    __shared__ int s[256];
    __shared__ int wred[8];
    int t = threadIdx.x;
    int lane = t & 31, wid = t >> 5;

    int bv = (t < blockIdx.x) ? g_bsum[t] : 0;
#pragma unroll
    for (int off = 16; off > 0; off >>= 1)
        bv += __shfl_xor_sync(0xFFFFFFFF, bv, off);
    if (lane == 0) wred[wid] = bv;

    int i = blockIdx.x * 256 + t;
    int c = (i < N) ? g_cnt[i] : 0;
    s[t] = c;
    __syncthreads();
#pragma unroll
    for (int off = 1; off < 256; off <<= 1) {
        int u = (t >= off) ? s[t - off] : 0;
        __syncthreads();
        s[t] += u;
        __syncthreads();
    }
    int boff = wred[0] + wred[1] + wred[2] + wred[3]
             + wred[4] + wred[5] + wred[6] + wred[7];
    if (i < N) {
        g_rowptr[i] = s[t] - c + boff;
        g_cnt[i] = 0;
        if (i == N - 1) g_rowptr[N] = Etot;
    }
}

__global__ void k_scatter(const void* __restrict__ ei, int E, int Etot) {
    int e = blockIdx.x * blockDim.x + threadIdx.x;
    if (e >= Etot) return;
    int src, dst;
    if (e < E) load_edge(ei, E, e, src, dst);
    else       src = dst = e - E;
    int pos = g_rowptr[dst] + atomicAdd(&g_cnt[dst], 1);
    g_col[pos] = src;
}

// ---------------- layer1 GEMM + fused logits, 8x8 tiles -------------------
// 128 threads = 8 cg (x8 chans) x 16 ng (x8 nodes); 128 nodes/block.
// K split 2x64; per k-step: 32B w + 32B x -> 64 FMAs (1 B/FMA).
// Each thread's 8 chans = one full head -> logits computed in-thread.
__global__ void __launch_bounds__(128) k_gemm1(const float* __restrict__ x,
                                               const float* __restrict__ W1,
                                               const float* __restrict__ att_s,
                                               const float* __restrict__ att_d,
                                               int N) {
    __shared__ float ws[64 * HC1];       // 16KB [k][c], half-K
    __shared__ float xs[64 * 128];       // 32KB [k][n], half-K, 128 nodes
    int tid = threadIdx.x;
    int nbase = blockIdx.x * 128;
    int cg = tid & 7, ng = tid >> 3;
    int c0 = cg * 8, n0 = ng * 8;
    unsigned long long acc[8][4] = {};   // [node][chpair]

    for (int half = 0; half < 2; half++) {
        {
            const float4* W4 = (const float4*)(W1 + half * 64 * HC1);
            float4* ws4 = (float4*)ws;
            for (int i = tid; i < 64 * HC1 / 4; i += 128) ws4[i] = W4[i];
        }
        for (int i = tid; i < 128 * 16; i += 128) {
            int n = i & 127, k4 = i >> 7;
            int gn = nbase + n;
            float4 v = (gn < N)
                ? ((const float4*)x)[(size_t)gn * 32 + half * 16 + k4]
                : make_float4(0.f, 0.f, 0.f, 0.f);
            xs[(k4 * 4 + 0) * 128 + n] = v.x;
            xs[(k4 * 4 + 1) * 128 + n] = v.y;
            xs[(k4 * 4 + 2) * 128 + n] = v.z;
            xs[(k4 * 4 + 3) * 128 + n] = v.w;
        }
        __syncthreads();
#pragma unroll 8
        for (int k = 0; k < 64; k++) {
            const ulonglong2* wp = (const ulonglong2*)(ws + k * HC1 + c0);
            ulonglong2 wv0 = wp[0];   // chans c0..c0+3
            ulonglong2 wv1 = wp[1];   // chans c0+4..c0+7
            const float4* xp = (const float4*)(xs + k * 128 + n0);
            float4 xa = xp[0];
            float4 xb = xp[1];
            unsigned long long xd[8];
            xd[0] = dup2(xa.x); xd[1] = dup2(xa.y); xd[2] = dup2(xa.z); xd[3] = dup2(xa.w);
            xd[4] = dup2(xb.x); xd[5] = dup2(xb.y); xd[6] = dup2(xb.z); xd[7] = dup2(xb.w);
#pragma unroll
            for (int i = 0; i < 8; i++) {
                fma2(acc[i][0], xd[i], wv0.x, acc[i][0]);
                fma2(acc[i][1], xd[i], wv0.y, acc[i][1]);
                fma2(acc[i][2], xd[i], wv1.x, acc[i][2]);
                fma2(acc[i][3], xd[i], wv1.y, acc[i][3]);
            }
        }
        __syncthreads();
    }

    float sa[8], da[8];
#pragma unroll
    for (int j = 0; j < 8; j++) { sa[j] = att_s[c0 + j]; da[j] = att_d[c0 + j]; }
#pragma unroll
    for (int i = 0; i < 8; i++) {
        float a[8];
        unpack2(acc[i][0], a[0], a[1]);
        unpack2(acc[i][1], a[2], a[3]);
        unpack2(acc[i][2], a[4], a[5]);
        unpack2(acc[i][3], a[6], a[7]);
        int gn = nbase + n0 + i;
        if (gn < N) {
            __half2 p0 = __floats2half2_rn(a[0], a[1]);
            __half2 p1 = __floats2half2_rn(a[2], a[3]);
            __half2 p2 = __floats2half2_rn(a[4], a[5]);
            __half2 p3 = __floats2half2_rn(a[6], a[7]);
            uint4 pk;
            pk.x = *(unsigned*)&p0; pk.y = *(unsigned*)&p1;
            pk.z = *(unsigned*)&p2; pk.w = *(unsigned*)&p3;
            *((uint4*)&g_h1[gn * HC1 + c0]) = pk;
            float s = 0.f, d = 0.f;
#pragma unroll
            for (int j = 0; j < 8; j++) {
                s = fmaf(a[j], sa[j], s);
                d = fmaf(a[j], da[j], d);
            }
            g_as1[gn * H1 + cg] = s;   // head == cg (8 chans per head)
            g_ad1[gn * H1 + cg] = d;
        }
    }
}

// ---------------- layer1 aggregate: warp/dst, 4x pipelined ----------------
__global__ void k_agg1(const float* __restrict__ b1, int N) {
    int w = (blockIdx.x * blockDim.x + threadIdx.x) >> 5;
    if (w >= N) return;
    int lane = threadIdx.x & 31;
    int head = lane >> 2, q = lane & 3;
    int r0 = g_rowptr[w], r1 = g_rowptr[w + 1];
    float adv = g_ad1[w * H1 + head];
    float s = 0.f, a0 = 0.f, a1 = 0.f;
    int i = r0;
    for (; i + 4 <= r1; i += 4) {
        int s0 = g_col[i], s1 = g_col[i+1], s2 = g_col[i+2], s3 = g_col[i+3];
        float l0 = g_as1[s0 * H1 + head];
        float l1 = g_as1[s1 * H1 + head];
        float l2 = g_as1[s2 * H1 + head];
        float l3 = g_as1[s3 * H1 + head];
        __half2 p0 = *(const __half2*)&g_h1[s0 * HC1 + head * C1 + q * 2];
        __half2 p1 = *(const __half2*)&g_h1[s1 * HC1 + head * C1 + q * 2];
        __half2 p2 = *(const __half2*)&g_h1[s2 * HC1 + head * C1 + q * 2];
        __half2 p3 = *(const __half2*)&g_h1[s3 * HC1 + head * C1 + q * 2];
        float e0 = __expf(leaky(l0 + adv));
        float e1 = __expf(leaky(l1 + adv));
        float e2 = __expf(leaky(l2 + adv));
        float e3 = __expf(leaky(l3 + adv));
        s += (e0 + e1) + (e2 + e3);
        float2 h0 = __half22float2(p0), h1v = __half22float2(p1);
        float2 h2v = __half22float2(p2), h3 = __half22float2(p3);
        a0 = fmaf(e0, h0.x, a0);  a1 = fmaf(e0, h0.y, a1);
        a0 = fmaf(e1, h1v.x, a0); a1 = fmaf(e1, h1v.y, a1);
        a0 = fmaf(e2, h2v.x, a0); a1 = fmaf(e2, h2v.y, a1);
        a0 = fmaf(e3, h3.x, a0);  a1 = fmaf(e3, h3.y, a1);
    }
    for (; i < r1; i++) {
        int src = g_col[i];
        float ex = __expf(leaky(g_as1[src * H1 + head] + adv));
        s += ex;
        float2 hv = __half22float2(*(const __half2*)&g_h1[src * HC1 + head * C1 + q * 2]);
        a0 = fmaf(ex, hv.x, a0);
        a1 = fmaf(ex, hv.y, a1);
    }
    s = (s > 0.f) ? s : 1.f;
    int j = head * C1 + q * 2;
    float v0 = a0 / s + b1[j];
    float v1 = a1 / s + b1[j + 1];
    float2 r;
    r.x = v0 > 0.f ? v0 : expm1f(v0);
    r.y = v1 > 0.f ? v1 : expm1f(v1);
    *(float2*)&g_x2[w * HC1 + j] = r;
}

// ---------------- layer2 GEMM + fused logits, 8x8 tiles -------------------
// 256 threads = 16 cg (x8 chans) x 16 ng (x8 nodes); 128 nodes/block.
// K split 2x32; per k-step: 32B w + 32B x -> 64 FMAs (1 B/FMA).
__global__ void __launch_bounds__(256) k_gemm2(const float* __restrict__ W2,
                                               const float* __restrict__ att_s,
                                               const float* __restrict__ att_d,
                                               int N) {
    __shared__ float ws[32 * FF];        // 16KB [k][c], half-K (32)
    __shared__ float xs[32 * 128];       // 16KB [k][n], half-K, 128 nodes
    int tid = threadIdx.x;
    int nbase = blockIdx.x * 128;
    int cg = tid & 15, ng = tid >> 4;
    int c0 = cg * 8, n0 = ng * 8;
    unsigned long long acc[8][4] = {};

    for (int half = 0; half < 2; half++) {
        {
            const float4* W4 = (const float4*)(W2 + half * 32 * FF);
            float4* ws4 = (float4*)ws;
            for (int i = tid; i < 32 * FF / 4; i += 256) ws4[i] = W4[i];
        }
        for (int i = tid; i < 128 * 8; i += 256) {
            int n = i & 127, k4 = i >> 7;
            int gn = nbase + n;
            float4 v = (gn < N)
                ? ((const float4*)g_x2)[(size_t)gn * 16 + half * 8 + k4]
                : make_float4(0.f, 0.f, 0.f, 0.f);
            xs[(k4 * 4 + 0) * 128 + n] = v.x;
            xs[(k4 * 4 + 1) * 128 + n] = v.y;
            xs[(k4 * 4 + 2) * 128 + n] = v.z;
            xs[(k4 * 4 + 3) * 128 + n] = v.w;
        }
        __syncthreads();
#pragma unroll 8
        for (int k = 0; k < 32; k++) {
            const ulonglong2* wp = (const ulonglong2*)(ws + k * FF + c0);
            ulonglong2 wv0 = wp[0];
            ulonglong2 wv1 = wp[1];
            const float4* xp = (const float4*)(xs + k * 128 + n0);
            float4 xa = xp[0];
            float4 xb = xp[1];
            unsigned long long xd[8];
            xd[0] = dup2(xa.x); xd[1] = dup2(xa.y); xd[2] = dup2(xa.z); xd[3] = dup2(xa.w);
            xd[4] = dup2(xb.x); xd[5] = dup2(xb.y); xd[6] = dup2(xb.z); xd[7] = dup2(xb.w);
#pragma unroll
            for (int i = 0; i < 8; i++) {
                fma2(acc[i][0], xd[i], wv0.x, acc[i][0]);
                fma2(acc[i][1], xd[i], wv0.y, acc[i][1]);
                fma2(acc[i][2], xd[i], wv1.x, acc[i][2]);
                fma2(acc[i][3], xd[i], wv1.y, acc[i][3]);
            }
        }
        __syncthreads();
    }

    float sa[8], da[8];
#pragma unroll
    for (int j = 0; j < 8; j++) { sa[j] = att_s[c0 + j]; da[j] = att_d[c0 + j]; }
#pragma unroll
    for (int i = 0; i < 8; i++) {
        float a[8];
        unpack2(acc[i][0], a[0], a[1]);
        unpack2(acc[i][1], a[2], a[3]);
        unpack2(acc[i][2], a[4], a[5]);
        unpack2(acc[i][3], a[6], a[7]);
        int gn = nbase + n0 + i;
        if (gn < N) {
            __half2 p0 = __floats2half2_rn(a[0], a[1]);
            __half2 p1 = __floats2half2_rn(a[2], a[3]);
            __half2 p2 = __floats2half2_rn(a[4], a[5]);
            __half2 p3 = __floats2half2_rn(a[6], a[7]);
            uint4 pk;
            pk.x = *(unsigned*)&p0; pk.y = *(unsigned*)&p1;
            pk.z = *(unsigned*)&p2; pk.w = *(unsigned*)&p3;
            *((uint4*)&g_h2[gn * FF + c0]) = pk;
        }
        float s = 0.f, d = 0.f;
#pragma unroll
        for (int j = 0; j < 8; j++) {
            s = fmaf(a[j], sa[j], s);
            d = fmaf(a[j], da[j], d);
        }
        // reduce over 16 cg threads (cg = lane bits 0..3)
#pragma unroll
        for (int off = 8; off > 0; off >>= 1) {
            s += __shfl_xor_sync(0xFFFFFFFF, s, off);
            d += __shfl_xor_sync(0xFFFFFFFF, d, off);
        }
        if (cg == 0 && gn < N) {
            g_as2[gn] = s;
            g_ad2[gn] = d;
        }
    }
}

// ---------------- layer2 aggregate: warp/dst, 4x pipelined ----------------
__global__ void k_agg2(float* __restrict__ out, const float* __restrict__ b2, int N) {
    int w = (blockIdx.x * blockDim.x + threadIdx.x) >> 5;
    if (w >= N) return;
    int lane = threadIdx.x & 31;
    int r0 = g_rowptr[w], r1 = g_rowptr[w + 1];
    float adv = g_ad2[w];
    float s = 0.f;
    float4 acc = make_float4(0.f, 0.f, 0.f, 0.f);
    int i = r0;
    for (; i + 4 <= r1; i += 4) {
        int s0 = g_col[i], s1 = g_col[i+1], s2 = g_col[i+2], s3 = g_col[i+3];
        float l0 = g_as2[s0], l1 = g_as2[s1], l2 = g_as2[s2], l3 = g_as2[s3];
        uint2 w0 = ((const uint2*)&g_h2[s0 * FF])[lane];
        uint2 w1 = ((const uint2*)&g_h2[s1 * FF])[lane];
        uint2 w2 = ((const uint2*)&g_h2[s2 * FF])[lane];
        uint2 w3 = ((const uint2*)&g_h2[s3 * FF])[lane];
        float e0 = __expf(leaky(l0 + adv));
        float e1 = __expf(leaky(l1 + adv));
        float e2 = __expf(leaky(l2 + adv));
        float e3 = __expf(leaky(l3 + adv));
        s += (e0 + e1) + (e2 + e3);
        float2 a01, a23;
        a01 = __half22float2(*(const __half2*)&w0.x);
        a23 = __half22float2(*(const __half2*)&w0.y);
        acc.x = fmaf(e0, a01.x, acc.x); acc.y = fmaf(e0, a01.y, acc.y);
        acc.z = fmaf(e0, a23.x, acc.z); acc.w = fmaf(e0, a23.y, acc.w);
        a01 = __half22float2(*(const __half2*)&w1.x);
        a23 = __half22float2(*(const __half2*)&w1.y);
        acc.x = fmaf(e1, a01.x, acc.x); acc.y = fmaf(e1, a01.y, acc.y);
        acc.z = fmaf(e1, a23.x, acc.z); acc.w = fmaf(e1, a23.y, acc.w);
        a01 = __half22float2(*(const __half2*)&w2.x);
        a23 = __half22float2(*(const __half2*)&w2.y);
        acc.x = fmaf(e2, a01.x, acc.x); acc.y = fmaf(e2, a01.y, acc.y);
        acc.z = fmaf(e2, a23.x, acc.z); acc.w = fmaf(e2, a23.y, acc.w);
        a01 = __half22float2(*(const __half2*)&w3.x);
        a23 = __half22float2(*(const __half2*)&w3.y);
        acc.x = fmaf(e3, a01.x, acc.x); acc.y = fmaf(e3, a01.y, acc.y);
        acc.z = fmaf(e3, a23.x, acc.z); acc.w = fmaf(e3, a23.y, acc.w);
    }
    for (; i < r1; i++) {
        int src = g_col[i];
        float ex = __expf(leaky(g_as2[src] + adv));
        s += ex;
        uint2 raw = ((const uint2*)&g_h2[src * FF])[lane];
        float2 h01 = __half22float2(*(const __half2*)&raw.x);
        float2 h23 = __half22float2(*(const __half2*)&raw.y);
        acc.x = fmaf(ex, h01.x, acc.x);
        acc.y = fmaf(ex, h01.y, acc.y);
        acc.z = fmaf(ex, h23.x, acc.z);
        acc.w = fmaf(ex, h23.y, acc.w);
    }
    s = (s > 0.f) ? s : 1.f;
    float4 bv = ((const float4*)b2)[lane];
    float4 r;
    r.x = acc.x / s + bv.x;
    r.y = acc.y / s + bv.y;
    r.z = acc.z / s + bv.z;
    r.w = acc.w / s + bv.w;
    ((float4*)&out[w * FF])[lane] = r;
}

// ---------------- launcher (R9 structure; gemm1 at launch #4) -------------
extern "C" void kernel_launch(void* const* d_in, const int* in_sizes, int n_in,
                              void* d_out, int out_size) {
    const float* x   = (const float*)d_in[0];
    const void*  ei  = d_in[1];
    const float* W1  = (const float*)d_in[2];
    const float* as1 = (const float*)d_in[3];
    const float* ad1 = (const float*)d_in[4];
    const float* b1  = (const float*)d_in[5];
    const float* W2  = (const float*)d_in[6];
    const float* as2 = (const float*)d_in[7];
    const float* ad2 = (const float*)d_in[8];
    const float* b2  = (const float*)d_in[9];
    float*       out = (float*)d_out;

    int N    = in_sizes[0] / FF;     // 50000
    int E    = in_sizes[1] / 2;      // 800000
    int Etot = E + N;
    int nb   = (N + 255) / 256;      // 196 (<=256 required by k_scan2)

    k_zero_detect<<<nb, 256>>>((const int*)ei, N);
    k_hist<<<(Etot + 255) / 256, 256>>>(ei, E, Etot);
    k_bsum<<<nb, 256>>>(N);
    k_gemm1<<<(N + 127) / 128, 128>>>(x, W1, as1, ad1, N);   // launch #4
    k_scan2<<<nb, 256>>>(N, Etot);
    k_scatter<<<(Etot + 255) / 256, 256>>>(ei, E, Etot);

    k_agg1<<<(N * 32 + 255) / 256, 256>>>(b1, N);

    k_gemm2<<<(N + 127) / 128, 256>>>(W2, as2, ad2, N);
    k_agg2<<<(N * 32 + 255) / 256, 256>>>(out, b2, N);
}

// round 14
// speedup vs baseline: 1.0806x; 1.0023x over previous
#include <cuda_runtime.h>
#include <cuda_fp16.h>
#include <mma.h>
#include <math.h>

using namespace nvcuda;

// Fixed problem shape (per reference setup_inputs)
#define NN 50000
#define FF 128
#define H1 8
#define C1 8
#define HC1 64
#define EMAX 900000   // E (800000) + N (50000) self loops

// ---------------- device scratch (no allocation allowed) ----------------
__device__ __align__(16) __half g_h1[NN * HC1];  // layer1 features (fp16)
__device__ __align__(16) float  g_x2[NN * HC1];  // ELU(layer1 out) fp32
__device__ __align__(16) __half g_h2[NN * FF];   // layer2 features (fp16)
__device__ __align__(16) __half g_w1h[FF * HC1]; // W1 preconverted to fp16
__device__ float g_as1[NN * H1];
__device__ float g_ad1[NN * H1];
__device__ float g_as2[NN];
__device__ float g_ad2[NN];
__device__ int   g_rowptr[NN + 1];
__device__ int   g_cnt[NN];
__device__ int   g_col[EMAX];                    // src ids grouped by dst
__device__ int   g_bsum[256];
__device__ int   g_is64;

// ---------------- helpers ----------------
__device__ __forceinline__ float leaky(float x) { return x > 0.0f ? x : 0.2f * x; }

__device__ __forceinline__ void fma2(unsigned long long& d, unsigned long long a,
                                     unsigned long long b, unsigned long long c) {
    asm("fma.rn.f32x2 %0, %1, %2, %3;" : "=l"(d) : "l"(a), "l"(b), "l"(c));
}
__device__ __forceinline__ unsigned long long dup2(float x) {
    unsigned long long d;
    unsigned int u = __float_as_uint(x);
    asm("mov.b64 %0, {%1, %2};" : "=l"(d) : "r"(u), "r"(u));
    return d;
}
__device__ __forceinline__ void unpack2(unsigned long long v, float& lo, float& hi) {
    unsigned int a, b;
    asm("mov.b64 {%0, %1}, %2;" : "=r"(a), "=r"(b) : "l"(v));
    lo = __uint_as_float(a);
    hi = __uint_as_float(b);
}

__device__ __forceinline__ void load_edge(const void* ei, int E, int e,
                                          int& src, int& dst) {
    if (g_is64) {
        const long long* p = (const long long*)ei;
        src = (int)p[e]; dst = (int)p[E + e];
    } else {
        const int* p = (const int*)ei;
        src = p[e]; dst = p[E + e];
    }
}
__device__ __forceinline__ int load_dst(const void* ei, int E, int e) {
    if (g_is64) return (int)((const long long*)ei)[E + e];
    return ((const int*)ei)[E + e];
}

// ---------------- zero counts + dtype probe + W1->fp16 (fused) ------------
__global__ void k_zero_detect(const int* __restrict__ ei32,
                              const float* __restrict__ W1, int N) {
    int i = blockIdx.x * blockDim.x + threadIdx.x;
    if (i < N) g_cnt[i] = 0;
    if (i < FF * HC1) g_w1h[i] = __float2half(W1[i]);
    if (i == 0) {
        int is64 = 1;
#pragma unroll
        for (int k = 0; k < 8; k++)
            if (ei32[2 * k + 1] != 0) is64 = 0;
        g_is64 = is64;
    }
}

__global__ void k_hist(const void* __restrict__ ei, int E, int Etot) {
    int e = blockIdx.x * blockDim.x + threadIdx.x;
    if (e >= Etot) return;
    int dst = (e < E) ? load_dst(ei, E, e) : e - E;
    atomicAdd(&g_cnt[dst], 1);
}

__global__ void k_bsum(int N) {
    __shared__ int red[256];
    int i = blockIdx.x * 256 + threadIdx.x;
    red[threadIdx.x] = (i < N) ? g_cnt[i] : 0;
    __syncthreads();
#pragma unroll
    for (int off = 128; off > 0; off >>= 1) {
        if (threadIdx.x < off) red[threadIdx.x] += red[threadIdx.x + off];
        __syncthreads();
    }
    if (threadIdx.x == 0) g_bsum[blockIdx.x] = red[0];
}

// per-block local scan; each block reduces its own bsum prefix (nb <= 256)
__global__ void k_scan2(int N, int Etot) {
    __shared__ int s[256];
    __shared__ int wred[8];
    int t = threadIdx.x;
    int lane = t & 31, wid = t >> 5;

    int bv = (t < blockIdx.x) ? g_bsum[t] : 0;
#pragma unroll
    for (int off = 16; off > 0; off >>= 1)
        bv += __shfl_xor_sync(0xFFFFFFFF, bv, off);
    if (lane == 0) wred[wid] = bv;

    int i = blockIdx.x * 256 + t;
    int c = (i < N) ? g_cnt[i] : 0;
    s[t] = c;
    __syncthreads();
#pragma unroll
    for (int off = 1; off < 256; off <<= 1) {
        int u = (t >= off) ? s[t - off] : 0;
        __syncthreads();
        s[t] += u;
        __syncthreads();
    }
    int boff = wred[0] + wred[1] + wred[2] + wred[3]
             + wred[4] + wred[5] + wred[6] + wred[7];
    if (i < N) {
        g_rowptr[i] = s[t] - c + boff;
        g_cnt[i] = 0;
        if (i == N - 1) g_rowptr[N] = Etot;
    }
}

__global__ void k_scatter(const void* __restrict__ ei, int E, int Etot) {
    int e = blockIdx.x * blockDim.x + threadIdx.x;
    if (e >= Etot) return;
    int src, dst;
    if (e < E) load_edge(ei, E, e, src, dst);
    else       src = dst = e - E;
    int pos = g_rowptr[dst] + atomicAdd(&g_cnt[dst], 1);
    g_col[pos] = src;
}

// ---------------- layer1 GEMM on tensor cores (wmma fp16->fp32) -----------
// 128 nodes/block, 256 threads = 8 warps; warp w owns nodes [w*16, w*16+16),
// all 64 channels (4 m16n16k16 C fragments). K = 128 in 8 steps.
// Epilogue: C -> smem fp32, per-head logits + fp16 h1 store.
__global__ void __launch_bounds__(256) k_gemm1(const float* __restrict__ x,
                                               const float* __restrict__ att_s,
                                               const float* __restrict__ att_d,
                                               int N) {
    __shared__ __align__(16) char smbuf[49152];
    __half* xsh = (__half*)smbuf;              // A: [128 nodes][128 k] 32KB
    __half* wsh = (__half*)(smbuf + 32768);    // B: [128 k][64 c]    16KB
    int tid = threadIdx.x;
    int w = tid >> 5, lane = tid & 31;
    int nbase = blockIdx.x * 128;

    // fill wsh from preconverted g_w1h (16KB copy)
    {
        const uint4* src = (const uint4*)g_w1h;
        uint4* dst = (uint4*)wsh;
        for (int i = tid; i < (FF * HC1) / 8; i += 256) dst[i] = src[i];
    }
    // fill xsh: fp32 x -> fp16
    for (int i = tid; i < 128 * 32; i += 256) {   // 128 nodes x 32 float4
        int n = i >> 5, k4 = i & 31;
        int gn = nbase + n;
        float4 v = (gn < N) ? ((const float4*)x)[(size_t)gn * 32 + k4]
                            : make_float4(0.f, 0.f, 0.f, 0.f);
        *(__half2*)&xsh[n * 128 + k4 * 4]     = __floats2half2_rn(v.x, v.y);
        *(__half2*)&xsh[n * 128 + k4 * 4 + 2] = __floats2half2_rn(v.z, v.w);
    }
    __syncthreads();

    wmma::fragment<wmma::accumulator, 16, 16, 16, float> c[4];
#pragma unroll
    for (int t = 0; t < 4; t++) wmma::fill_fragment(c[t], 0.0f);
    int r0 = w * 16;
#pragma unroll
    for (int k0 = 0; k0 < 8; k0++) {
        wmma::fragment<wmma::matrix_a, 16, 16, 16, __half, wmma::row_major> a;
        wmma::load_matrix_sync(a, xsh + r0 * 128 + k0 * 16, 128);
#pragma unroll
        for (int ct = 0; ct < 4; ct++) {
            wmma::fragment<wmma::matrix_b, 16, 16, 16, __half, wmma::row_major> b;
            wmma::load_matrix_sync(b, wsh + (k0 * 16) * 64 + ct * 16, 64);
            wmma::mma_sync(c[ct], a, b, c[ct]);
        }
    }
    __syncthreads();   // all warps done with xsh/wsh before reuse

    // epilogue scratch: warp w -> [16][72] fp32 at float offset w*1152
    float* epi = (float*)smbuf + w * 16 * 72;
#pragma unroll
    for (int ct = 0; ct < 4; ct++)
        wmma::store_matrix_sync(epi + ct * 16, c[ct], 72, wmma::mem_row_major);
    __syncwarp();

    // lane l owns channels cch, cch+1 of head l>>2
    int cch = (lane >> 2) * 8 + (lane & 3) * 2;
    int head = lane >> 2;
    float sa0 = att_s[cch], sa1 = att_s[cch + 1];
    float da0 = att_d[cch], da1 = att_d[cch + 1];
#pragma unroll
    for (int r = 0; r < 16; r++) {
        int gn = nbase + r0 + r;
        float2 h = *(float2*)&epi[r * 72 + cch];
        if (gn < N)
            *(__half2*)&g_h1[gn * HC1 + cch] = __floats2half2_rn(h.x, h.y);
        float s = h.x * sa0 + h.y * sa1;
        float d = h.x * da0 + h.y * da1;
        s += __shfl_xor_sync(0xFFFFFFFF, s, 1);
        d += __shfl_xor_sync(0xFFFFFFFF, d, 1);
        s += __shfl_xor_sync(0xFFFFFFFF, s, 2);
        d += __shfl_xor_sync(0xFFFFFFFF, d, 2);
        if ((lane & 3) == 0 && gn < N) {
            g_as1[gn * H1 + head] = s;
            g_ad1[gn * H1 + head] = d;
        }
    }
}

// ---------------- layer1 aggregate: warp/dst, 4x pipelined (R9) -----------
__global__ void k_agg1(const float* __restrict__ b1, int N) {
    int w = (blockIdx.x * blockDim.x + threadIdx.x) >> 5;
    if (w >= N) return;
    int lane = threadIdx.x & 31;
    int head = lane >> 2, q = lane & 3;
    int r0 = g_rowptr[w], r1 = g_rowptr[w + 1];
    float adv = g_ad1[w * H1 + head];
    float s = 0.f, a0 = 0.f, a1 = 0.f;
    int i = r0;
    for (; i + 4 <= r1; i += 4) {
        int s0 = g_col[i], s1 = g_col[i+1], s2 = g_col[i+2], s3 = g_col[i+3];
        float l0 = g_as1[s0 * H1 + head];
        float l1 = g_as1[s1 * H1 + head];
        float l2 = g_as1[s2 * H1 + head];
        float l3 = g_as1[s3 * H1 + head];
        __half2 p0 = *(const __half2*)&g_h1[s0 * HC1 + head * C1 + q * 2];
        __half2 p1 = *(const __half2*)&g_h1[s1 * HC1 + head * C1 + q * 2];
        __half2 p2 = *(const __half2*)&g_h1[s2 * HC1 + head * C1 + q * 2];
        __half2 p3 = *(const __half2*)&g_h1[s3 * HC1 + head * C1 + q * 2];
        float e0 = __expf(leaky(l0 + adv));
        float e1 = __expf(leaky(l1 + adv));
        float e2 = __expf(leaky(l2 + adv));
        float e3 = __expf(leaky(l3 + adv));
        s += (e0 + e1) + (e2 + e3);
        float2 h0 = __half22float2(p0), h1v = __half22float2(p1);
        float2 h2v = __half22float2(p2), h3 = __half22float2(p3);
        a0 = fmaf(e0, h0.x, a0);  a1 = fmaf(e0, h0.y, a1);
        a0 = fmaf(e1, h1v.x, a0); a1 = fmaf(e1, h1v.y, a1);
        a0 = fmaf(e2, h2v.x, a0); a1 = fmaf(e2, h2v.y, a1);
        a0 = fmaf(e3, h3.x, a0);  a1 = fmaf(e3, h3.y, a1);
    }
    for (; i < r1; i++) {
        int src = g_col[i];
        float ex = __expf(leaky(g_as1[src * H1 + head] + adv));
        s += ex;
        float2 hv = __half22float2(*(const __half2*)&g_h1[src * HC1 + head * C1 + q * 2]);
        a0 = fmaf(ex, hv.x, a0);
        a1 = fmaf(ex, hv.y, a1);
    }
    s = (s > 0.f) ? s : 1.f;
    int j = head * C1 + q * 2;
    float v0 = a0 / s + b1[j];
    float v1 = a1 / s + b1[j + 1];
    float2 r;
    r.x = v0 > 0.f ? v0 : expm1f(v0);
    r.y = v1 > 0.f ? v1 : expm1f(v1);
    *(float2*)&g_x2[w * HC1 + j] = r;
}

// ---------------- layer2 GEMM + fused logits (f32x2), fp16 h2 out (R9) ----
__global__ void __launch_bounds__(256) k_gemm2(const float* __restrict__ W2,
                                               const float* __restrict__ att_s,
                                               const float* __restrict__ att_d,
                                               int N) {
    __shared__ float ws[HC1 * FF];       // 32KB [k][c]
    __shared__ float xs[HC1 * 64];       // 16KB [k][n] transposed
    int tid = threadIdx.x;
    int nbase = blockIdx.x * 64;
    const float4* W4 = (const float4*)W2;
    float4* ws4 = (float4*)ws;
    for (int i = tid; i < HC1 * FF / 4; i += 256) ws4[i] = W4[i];
    for (int i = tid; i < 64 * 16; i += 256) {
        int n = i & 63, k4 = i >> 6;
        int gn = nbase + n;
        float4 v = (gn < N) ? ((const float4*)g_x2)[(size_t)gn * 16 + k4]
                            : make_float4(0.f, 0.f, 0.f, 0.f);
        xs[(k4 * 4 + 0) * 64 + n] = v.x;
        xs[(k4 * 4 + 1) * 64 + n] = v.y;
        xs[(k4 * 4 + 2) * 64 + n] = v.z;
        xs[(k4 * 4 + 3) * 64 + n] = v.w;
    }
    __syncthreads();
    int cg = tid & 31, ng = tid >> 5;
    int c0 = cg * 4, n0 = ng * 8;
    unsigned long long acc[8][2] = {};
#pragma unroll 16
    for (int k = 0; k < HC1; k++) {
        ulonglong2 wv = ((const ulonglong2*)(ws + k * FF))[cg];
        float4 xa = ((const float4*)(xs + k * 64))[ng * 2];
        float4 xb = ((const float4*)(xs + k * 64))[ng * 2 + 1];
        unsigned long long xd[8];
        xd[0] = dup2(xa.x); xd[1] = dup2(xa.y); xd[2] = dup2(xa.z); xd[3] = dup2(xa.w);
        xd[4] = dup2(xb.x); xd[5] = dup2(xb.y); xd[6] = dup2(xb.z); xd[7] = dup2(xb.w);
#pragma unroll
        for (int i = 0; i < 8; i++) {
            fma2(acc[i][0], xd[i], wv.x, acc[i][0]);
            fma2(acc[i][1], xd[i], wv.y, acc[i][1]);
        }
    }
    float4 sa = ((const float4*)att_s)[cg];
    float4 da = ((const float4*)att_d)[cg];
#pragma unroll
    for (int i = 0; i < 8; i++) {
        float a0, a1, a2, a3;
        unpack2(acc[i][0], a0, a1);
        unpack2(acc[i][1], a2, a3);
        int gn = nbase + n0 + i;
        if (gn < N) {
            *((__half2*)&g_h2[gn * FF + c0])     = __floats2half2_rn(a0, a1);
            *((__half2*)&g_h2[gn * FF + c0 + 2]) = __floats2half2_rn(a2, a3);
        }
        float s = a0*sa.x + a1*sa.y + a2*sa.z + a3*sa.w;
        float d = a0*da.x + a1*da.y + a2*da.z + a3*da.w;
#pragma unroll
        for (int off = 16; off > 0; off >>= 1) {
            s += __shfl_xor_sync(0xFFFFFFFF, s, off);
            d += __shfl_xor_sync(0xFFFFFFFF, d, off);
        }
        if (cg == 0 && gn < N) {
            g_as2[gn] = s;
            g_ad2[gn] = d;
        }
    }
}

// ---------------- layer2 aggregate: warp/dst, 4x pipelined (R9) -----------
__global__ void k_agg2(float* __restrict__ out, const float* __restrict__ b2, int N) {
    int w = (blockIdx.x * blockDim.x + threadIdx.x) >> 5;
    if (w >= N) return;
    int lane = threadIdx.x & 31;
    int r0 = g_rowptr[w], r1 = g_rowptr[w + 1];
    float adv = g_ad2[w];
    float s = 0.f;
    float4 acc = make_float4(0.f, 0.f, 0.f, 0.f);
    int i = r0;
    for (; i + 4 <= r1; i += 4) {
        int s0 = g_col[i], s1 = g_col[i+1], s2 = g_col[i+2], s3 = g_col[i+3];
        float l0 = g_as2[s0], l1 = g_as2[s1], l2 = g_as2[s2], l3 = g_as2[s3];
        uint2 w0 = ((const uint2*)&g_h2[s0 * FF])[lane];
        uint2 w1 = ((const uint2*)&g_h2[s1 * FF])[lane];
        uint2 w2 = ((const uint2*)&g_h2[s2 * FF])[lane];
        uint2 w3 = ((const uint2*)&g_h2[s3 * FF])[lane];
        float e0 = __expf(leaky(l0 + adv));
        float e1 = __expf(leaky(l1 + adv));
        float e2 = __expf(leaky(l2 + adv));
        float e3 = __expf(leaky(l3 + adv));
        s += (e0 + e1) + (e2 + e3);
        float2 a01, a23;
        a01 = __half22float2(*(const __half2*)&w0.x);
        a23 = __half22float2(*(const __half2*)&w0.y);
        acc.x = fmaf(e0, a01.x, acc.x); acc.y = fmaf(e0, a01.y, acc.y);
        acc.z = fmaf(e0, a23.x, acc.z); acc.w = fmaf(e0, a23.y, acc.w);
        a01 = __half22float2(*(const __half2*)&w1.x);
        a23 = __half22float2(*(const __half2*)&w1.y);
        acc.x = fmaf(e1, a01.x, acc.x); acc.y = fmaf(e1, a01.y, acc.y);
        acc.z = fmaf(e1, a23.x, acc.z); acc.w = fmaf(e1, a23.y, acc.w);
        a01 = __half22float2(*(const __half2*)&w2.x);
        a23 = __half22float2(*(const __half2*)&w2.y);
        acc.x = fmaf(e2, a01.x, acc.x); acc.y = fmaf(e2, a01.y, acc.y);
        acc.z = fmaf(e2, a23.x, acc.z); acc.w = fmaf(e2, a23.y, acc.w);
        a01 = __half22float2(*(const __half2*)&w3.x);
        a23 = __half22float2(*(const __half2*)&w3.y);
        acc.x = fmaf(e3, a01.x, acc.x); acc.y = fmaf(e3, a01.y, acc.y);
        acc.z = fmaf(e3, a23.x, acc.z); acc.w = fmaf(e3, a23.y, acc.w);
    }
    for (; i < r1; i++) {
        int src = g_col[i];
        float ex = __expf(leaky(g_as2[src] + adv));
        s += ex;
        uint2 raw = ((const uint2*)&g_h2[src * FF])[lane];
        float2 h01 = __half22float2(*(const __half2*)&raw.x);
        float2 h23 = __half22float2(*(const __half2*)&raw.y);
        acc.x = fmaf(ex, h01.x, acc.x);
        acc.y = fmaf(ex, h01.y, acc.y);
        acc.z = fmaf(ex, h23.x, acc.z);
        acc.w = fmaf(ex, h23.y, acc.w);
    }
    s = (s > 0.f) ? s : 1.f;
    float4 bv = ((const float4*)b2)[lane];
    float4 r;
    r.x = acc.x / s + bv.x;
    r.y = acc.y / s + bv.y;
    r.z = acc.z / s + bv.z;
    r.w = acc.w / s + bv.w;
    ((float4*)&out[w * FF])[lane] = r;
}

// ---------------- launcher (R9 structure; gemm1 at launch #4) -------------
extern "C" void kernel_launch(void* const* d_in, const int* in_sizes, int n_in,
                              void* d_out, int out_size) {
    const float* x   = (const float*)d_in[0];
    const void*  ei  = d_in[1];
    const float* W1  = (const float*)d_in[2];
    const float* as1 = (const float*)d_in[3];
    const float* ad1 = (const float*)d_in[4];
    const float* b1  = (const float*)d_in[5];
    const float* W2  = (const float*)d_in[6];
    const float* as2 = (const float*)d_in[7];
    const float* ad2 = (const float*)d_in[8];
    const float* b2  = (const float*)d_in[9];
    float*       out = (float*)d_out;

    int N    = in_sizes[0] / FF;     // 50000
    int E    = in_sizes[1] / 2;      // 800000
    int Etot = E + N;
    int nb   = (N + 255) / 256;      // 196 (<=256 required by k_scan2)

    k_zero_detect<<<nb, 256>>>((const int*)ei, W1, N);
    k_hist<<<(Etot + 255) / 256, 256>>>(ei, E, Etot);
    k_bsum<<<nb, 256>>>(N);
    k_gemm1<<<(N + 127) / 128, 256>>>(x, as1, ad1, N);   // launch #4 (profiled)
    k_scan2<<<nb, 256>>>(N, Etot);
    k_scatter<<<(Etot + 255) / 256, 256>>>(ei, E, Etot);

    k_agg1<<<(N * 32 + 255) / 256, 256>>>(b1, N);

    k_gemm2<<<(N + 63) / 64, 256>>>(W2, as2, ad2, N);
    k_agg2<<<(N * 32 + 255) / 256, 256>>>(out, b2, N);
}

// round 15
// speedup vs baseline: 1.1110x; 1.0282x over previous
#include <cuda_runtime.h>
#include <cuda_fp16.h>
#include <math.h>

// Fixed problem shape (per reference setup_inputs)
#define NN 50000
#define FF 128
#define H1 8
#define C1 8
#define HC1 64
#define EMAX 900000   // E (800000) + N (50000) self loops

// ---------------- device scratch (no allocation allowed) ----------------
__device__ __align__(16) __half g_h1[NN * HC1];  // layer1 features (fp16)
__device__ __align__(16) float  g_x2[NN * HC1];  // ELU(layer1 out) fp32
__device__ __align__(16) __half g_h2[NN * FF];   // layer2 features (fp16)
__device__ float g_as1[NN * H1];
__device__ float g_ad1[NN * H1];
__device__ float g_as2[NN];
__device__ float g_ad2[NN];
__device__ int   g_rowptr[NN + 1];
__device__ int   g_cnt[NN];
__device__ int   g_col[EMAX];                    // src ids grouped by dst
__device__ int   g_bsum[256];
__device__ int   g_is64;

// ---------------- helpers ----------------
__device__ __forceinline__ float leaky(float x) { return x > 0.0f ? x : 0.2f * x; }

__device__ __forceinline__ void fma2(unsigned long long& d, unsigned long long a,
                                     unsigned long long b, unsigned long long c) {
    asm("fma.rn.f32x2 %0, %1, %2, %3;" : "=l"(d) : "l"(a), "l"(b), "l"(c));
}
__device__ __forceinline__ unsigned long long dup2(float x) {
    unsigned long long d;
    unsigned int u = __float_as_uint(x);
    asm("mov.b64 %0, {%1, %2};" : "=l"(d) : "r"(u), "r"(u));
    return d;
}
__device__ __forceinline__ void unpack2(unsigned long long v, float& lo, float& hi) {
    unsigned int a, b;
    asm("mov.b64 {%0, %1}, %2;" : "=r"(a), "=r"(b) : "l"(v));
    lo = __uint_as_float(a);
    hi = __uint_as_float(b);
}

__device__ __forceinline__ void load_edge(const void* ei, int E, int e,
                                          int& src, int& dst) {
    if (g_is64) {
        const long long* p = (const long long*)ei;
        src = (int)p[e]; dst = (int)p[E + e];
    } else {
        const int* p = (const int*)ei;
        src = p[e]; dst = p[E + e];
    }
}
__device__ __forceinline__ int load_dst(const void* ei, int E, int e) {
    if (g_is64) return (int)((const long long*)ei)[E + e];
    return ((const int*)ei)[E + e];
}

// ---------------- zero counts + dtype probe (fused) ----------------------
__global__ void k_zero_detect(const int* __restrict__ ei32, int N) {
    int i = blockIdx.x * blockDim.x + threadIdx.x;
    if (i < N) g_cnt[i] = 0;
    if (blockIdx.x == 0 && threadIdx.x == 0) {
        int is64 = 1;
#pragma unroll
        for (int k = 0; k < 8; k++)
            if (ei32[2 * k + 1] != 0) is64 = 0;
        g_is64 = is64;
    }
}

__global__ void k_hist(const void* __restrict__ ei, int E, int Etot) {
    int e = blockIdx.x * blockDim.x + threadIdx.x;
    if (e >= Etot) return;
    int dst = (e < E) ? load_dst(ei, E, e) : e - E;
    atomicAdd(&g_cnt[dst], 1);
}

__global__ void k_bsum(int N) {
    __shared__ int red[256];
    int i = blockIdx.x * 256 + threadIdx.x;
    red[threadIdx.x] = (i < N) ? g_cnt[i] : 0;
    __syncthreads();
#pragma unroll
    for (int off = 128; off > 0; off >>= 1) {
        if (threadIdx.x < off) red[threadIdx.x] += red[threadIdx.x + off];
        __syncthreads();
    }
    if (threadIdx.x == 0) g_bsum[blockIdx.x] = red[0];
}

// per-block local scan; each block reduces its own bsum prefix (nb <= 256)
__global__ void k_scan2(int N, int Etot) {
    __shared__ int s[256];
    __shared__ int wred[8];
    int t = threadIdx.x;
    int lane = t & 31, wid = t >> 5;

    int bv = (t < blockIdx.x) ? g_bsum[t] : 0;
#pragma unroll
    for (int off = 16; off > 0; off >>= 1)
        bv += __shfl_xor_sync(0xFFFFFFFF, bv, off);
    if (lane == 0) wred[wid] = bv;

    int i = blockIdx.x * 256 + t;
    int c = (i < N) ? g_cnt[i] : 0;
    s[t] = c;
    __syncthreads();
#pragma unroll
    for (int off = 1; off < 256; off <<= 1) {
        int u = (t >= off) ? s[t - off] : 0;
        __syncthreads();
        s[t] += u;
        __syncthreads();
    }
    int boff = wred[0] + wred[1] + wred[2] + wred[3]
             + wred[4] + wred[5] + wred[6] + wred[7];
    if (i < N) {
        g_rowptr[i] = s[t] - c + boff;
        g_cnt[i] = 0;
        if (i == N - 1) g_rowptr[N] = Etot;
    }
}

__global__ void k_scatter(const void* __restrict__ ei, int E, int Etot) {
    int e = blockIdx.x * blockDim.x + threadIdx.x;
    if (e >= Etot) return;
    int src, dst;
    if (e < E) load_edge(ei, E, e, src, dst);
    else       src = dst = e - E;
    int pos = g_rowptr[dst] + atomicAdd(&g_cnt[dst], 1);
    g_col[pos] = src;
}

// ---------------- layer1 GEMM + fused logits (batched-MLP fills) ----------
// 128 nodes/block, K split into 2 halves of 64 (smem 48KB).
// Fill loads staged in registers (MLP 8-12/warp) before smem stores.
__global__ void __launch_bounds__(256) k_gemm1(const float* __restrict__ x,
                                               const float* __restrict__ W1,
                                               const float* __restrict__ att_s,
                                               const float* __restrict__ att_d,
                                               int N) {
    __shared__ float ws[64 * HC1];       // 16KB [k][c], half-K
    __shared__ float xs[64 * 128];       // 32KB [k][n], half-K, 128 nodes
    int tid = threadIdx.x;
    int nbase = blockIdx.x * 128;
    int cg = tid & 15, ng = tid >> 4;
    int c0 = cg * 4, n0 = ng * 8;
    unsigned long long acc[8][2] = {};

    for (int half = 0; half < 2; half++) {
        // stage ALL fill loads first -> high MLP, stream at DRAM bandwidth
        float4 wtmp[4];
        {
            const float4* W4 = (const float4*)(W1 + half * 64 * HC1);
#pragma unroll
            for (int j = 0; j < 4; j++) wtmp[j] = W4[tid + j * 256];
        }
        float4 xtmp[8];
#pragma unroll
        for (int j = 0; j < 8; j++) {
            int i = tid + j * 256;
            int n = i & 127, k4 = i >> 7;
            int gn = nbase + n;
            xtmp[j] = (gn < N)
                ? ((const float4*)x)[(size_t)gn * 32 + half * 16 + k4]
                : make_float4(0.f, 0.f, 0.f, 0.f);
        }
        {
            float4* ws4 = (float4*)ws;
#pragma unroll
            for (int j = 0; j < 4; j++) ws4[tid + j * 256] = wtmp[j];
        }
#pragma unroll
        for (int j = 0; j < 8; j++) {
            int i = tid + j * 256;
            int n = i & 127, k4 = i >> 7;
            xs[(k4 * 4 + 0) * 128 + n] = xtmp[j].x;
            xs[(k4 * 4 + 1) * 128 + n] = xtmp[j].y;
            xs[(k4 * 4 + 2) * 128 + n] = xtmp[j].z;
            xs[(k4 * 4 + 3) * 128 + n] = xtmp[j].w;
        }
        __syncthreads();
#pragma unroll 16
        for (int k = 0; k < 64; k++) {
            ulonglong2 wv = ((const ulonglong2*)(ws + k * HC1))[cg];
            float4 xa = ((const float4*)(xs + k * 128))[ng * 2];
            float4 xb = ((const float4*)(xs + k * 128))[ng * 2 + 1];
            unsigned long long xd[8];
            xd[0] = dup2(xa.x); xd[1] = dup2(xa.y); xd[2] = dup2(xa.z); xd[3] = dup2(xa.w);
            xd[4] = dup2(xb.x); xd[5] = dup2(xb.y); xd[6] = dup2(xb.z); xd[7] = dup2(xb.w);
#pragma unroll
            for (int i = 0; i < 8; i++) {
                fma2(acc[i][0], xd[i], wv.x, acc[i][0]);
                fma2(acc[i][1], xd[i], wv.y, acc[i][1]);
            }
        }
        __syncthreads();
    }

    float sa0 = att_s[c0], sa1 = att_s[c0+1], sa2 = att_s[c0+2], sa3 = att_s[c0+3];
    float da0 = att_d[c0], da1 = att_d[c0+1], da2 = att_d[c0+2], da3 = att_d[c0+3];
    int head = cg >> 1;
#pragma unroll
    for (int i = 0; i < 8; i++) {
        float a0, a1, a2, a3;
        unpack2(acc[i][0], a0, a1);
        unpack2(acc[i][1], a2, a3);
        int gn = nbase + n0 + i;
        if (gn < N) {
            *((__half2*)&g_h1[gn * HC1 + c0])     = __floats2half2_rn(a0, a1);
            *((__half2*)&g_h1[gn * HC1 + c0 + 2]) = __floats2half2_rn(a2, a3);
        }
        float s = a0*sa0 + a1*sa1 + a2*sa2 + a3*sa3;
        float d = a0*da0 + a1*da1 + a2*da2 + a3*da3;
        s += __shfl_xor_sync(0xFFFFFFFF, s, 1);
        d += __shfl_xor_sync(0xFFFFFFFF, d, 1);
        if ((cg & 1) == 0 && gn < N) {
            g_as1[gn * H1 + head] = s;
            g_ad1[gn * H1 + head] = d;
        }
    }
}

// ---------------- layer1 aggregate: warp/dst, 4x pipelined (R9) -----------
__global__ void k_agg1(const float* __restrict__ b1, int N) {
    int w = (blockIdx.x * blockDim.x + threadIdx.x) >> 5;
    if (w >= N) return;
    int lane = threadIdx.x & 31;
    int head = lane >> 2, q = lane & 3;
    int r0 = g_rowptr[w], r1 = g_rowptr[w + 1];
    float adv = g_ad1[w * H1 + head];
    float s = 0.f, a0 = 0.f, a1 = 0.f;
    int i = r0;
    for (; i + 4 <= r1; i += 4) {
        int s0 = g_col[i], s1 = g_col[i+1], s2 = g_col[i+2], s3 = g_col[i+3];
        float l0 = g_as1[s0 * H1 + head];
        float l1 = g_as1[s1 * H1 + head];
        float l2 = g_as1[s2 * H1 + head];
        float l3 = g_as1[s3 * H1 + head];
        __half2 p0 = *(const __half2*)&g_h1[s0 * HC1 + head * C1 + q * 2];
        __half2 p1 = *(const __half2*)&g_h1[s1 * HC1 + head * C1 + q * 2];
        __half2 p2 = *(const __half2*)&g_h1[s2 * HC1 + head * C1 + q * 2];
        __half2 p3 = *(const __half2*)&g_h1[s3 * HC1 + head * C1 + q * 2];
        float e0 = __expf(leaky(l0 + adv));
        float e1 = __expf(leaky(l1 + adv));
        float e2 = __expf(leaky(l2 + adv));
        float e3 = __expf(leaky(l3 + adv));
        s += (e0 + e1) + (e2 + e3);
        float2 h0 = __half22float2(p0), h1v = __half22float2(p1);
        float2 h2v = __half22float2(p2), h3 = __half22float2(p3);
        a0 = fmaf(e0, h0.x, a0);  a1 = fmaf(e0, h0.y, a1);
        a0 = fmaf(e1, h1v.x, a0); a1 = fmaf(e1, h1v.y, a1);
        a0 = fmaf(e2, h2v.x, a0); a1 = fmaf(e2, h2v.y, a1);
        a0 = fmaf(e3, h3.x, a0);  a1 = fmaf(e3, h3.y, a1);
    }
    for (; i < r1; i++) {
        int src = g_col[i];
        float ex = __expf(leaky(g_as1[src * H1 + head] + adv));
        s += ex;
        float2 hv = __half22float2(*(const __half2*)&g_h1[src * HC1 + head * C1 + q * 2]);
        a0 = fmaf(ex, hv.x, a0);
        a1 = fmaf(ex, hv.y, a1);
    }
    s = (s > 0.f) ? s : 1.f;
    int j = head * C1 + q * 2;
    float v0 = a0 / s + b1[j];
    float v1 = a1 / s + b1[j + 1];
    float2 r;
    r.x = v0 > 0.f ? v0 : expm1f(v0);
    r.y = v1 > 0.f ? v1 : expm1f(v1);
    *(float2*)&g_x2[w * HC1 + j] = r;
}

// ---------------- layer2 GEMM + fused logits (batched-MLP fills) ----------
// 64 nodes/block (R9 shape), staged fills.
__global__ void __launch_bounds__(256) k_gemm2(const float* __restrict__ W2,
                                               const float* __restrict__ att_s,
                                               const float* __restrict__ att_d,
                                               int N) {
    __shared__ float ws[HC1 * FF];       // 32KB [k][c]
    __shared__ float xs[HC1 * 64];       // 16KB [k][n] transposed
    int tid = threadIdx.x;
    int nbase = blockIdx.x * 64;

    // stage ALL fill loads (8 W float4 + 4 x float4 per thread)
    float4 wtmp[8];
    {
        const float4* W4 = (const float4*)W2;
#pragma unroll
        for (int j = 0; j < 8; j++) wtmp[j] = W4[tid + j * 256];
    }
    float4 xtmp[4];
#pragma unroll
    for (int j = 0; j < 4; j++) {
        int i = tid + j * 256;
        int n = i & 63, k4 = i >> 6;
        int gn = nbase + n;
        xtmp[j] = (gn < N) ? ((const float4*)g_x2)[(size_t)gn * 16 + k4]
                           : make_float4(0.f, 0.f, 0.f, 0.f);
    }
    {
        float4* ws4 = (float4*)ws;
#pragma unroll
        for (int j = 0; j < 8; j++) ws4[tid + j * 256] = wtmp[j];
    }
#pragma unroll
    for (int j = 0; j < 4; j++) {
        int i = tid + j * 256;
        int n = i & 63, k4 = i >> 6;
        xs[(k4 * 4 + 0) * 64 + n] = xtmp[j].x;
        xs[(k4 * 4 + 1) * 64 + n] = xtmp[j].y;
        xs[(k4 * 4 + 2) * 64 + n] = xtmp[j].z;
        xs[(k4 * 4 + 3) * 64 + n] = xtmp[j].w;
    }
    __syncthreads();
    int cg = tid & 31, ng = tid >> 5;
    int c0 = cg * 4, n0 = ng * 8;
    unsigned long long acc[8][2] = {};
#pragma unroll 16
    for (int k = 0; k < HC1; k++) {
        ulonglong2 wv = ((const ulonglong2*)(ws + k * FF))[cg];
        float4 xa = ((const float4*)(xs + k * 64))[ng * 2];
        float4 xb = ((const float4*)(xs + k * 64))[ng * 2 + 1];
        unsigned long long xd[8];
        xd[0] = dup2(xa.x); xd[1] = dup2(xa.y); xd[2] = dup2(xa.z); xd[3] = dup2(xa.w);
        xd[4] = dup2(xb.x); xd[5] = dup2(xb.y); xd[6] = dup2(xb.z); xd[7] = dup2(xb.w);
#pragma unroll
        for (int i = 0; i < 8; i++) {
            fma2(acc[i][0], xd[i], wv.x, acc[i][0]);
            fma2(acc[i][1], xd[i], wv.y, acc[i][1]);
        }
    }
    float4 sa = ((const float4*)att_s)[cg];
    float4 da = ((const float4*)att_d)[cg];
#pragma unroll
    for (int i = 0; i < 8; i++) {
        float a0, a1, a2, a3;
        unpack2(acc[i][0], a0, a1);
        unpack2(acc[i][1], a2, a3);
        int gn = nbase + n0 + i;
        if (gn < N) {
            *((__half2*)&g_h2[gn * FF + c0])     = __floats2half2_rn(a0, a1);
            *((__half2*)&g_h2[gn * FF + c0 + 2]) = __floats2half2_rn(a2, a3);
        }
        float s = a0*sa.x + a1*sa.y + a2*sa.z + a3*sa.w;
        float d = a0*da.x + a1*da.y + a2*da.z + a3*da.w;
#pragma unroll
        for (int off = 16; off > 0; off >>= 1) {
            s += __shfl_xor_sync(0xFFFFFFFF, s, off);
            d += __shfl_xor_sync(0xFFFFFFFF, d, off);
        }
        if (cg == 0 && gn < N) {
            g_as2[gn] = s;
            g_ad2[gn] = d;
        }
    }
}

// ---------------- layer2 aggregate: warp/dst, 4x pipelined (R9) -----------
__global__ void k_agg2(float* __restrict__ out, const float* __restrict__ b2, int N) {
    int w = (blockIdx.x * blockDim.x + threadIdx.x) >> 5;
    if (w >= N) return;
    int lane = threadIdx.x & 31;
    int r0 = g_rowptr[w], r1 = g_rowptr[w + 1];
    float adv = g_ad2[w];
    float s = 0.f;
    float4 acc = make_float4(0.f, 0.f, 0.f, 0.f);
    int i = r0;
    for (; i + 4 <= r1; i += 4) {
        int s0 = g_col[i], s1 = g_col[i+1], s2 = g_col[i+2], s3 = g_col[i+3];
        float l0 = g_as2[s0], l1 = g_as2[s1], l2 = g_as2[s2], l3 = g_as2[s3];
        uint2 w0 = ((const uint2*)&g_h2[s0 * FF])[lane];
        uint2 w1 = ((const uint2*)&g_h2[s1 * FF])[lane];
        uint2 w2 = ((const uint2*)&g_h2[s2 * FF])[lane];
        uint2 w3 = ((const uint2*)&g_h2[s3 * FF])[lane];
        float e0 = __expf(leaky(l0 + adv));
        float e1 = __expf(leaky(l1 + adv));
        float e2 = __expf(leaky(l2 + adv));
        float e3 = __expf(leaky(l3 + adv));
        s += (e0 + e1) + (e2 + e3);
        float2 a01, a23;
        a01 = __half22float2(*(const __half2*)&w0.x);
        a23 = __half22float2(*(const __half2*)&w0.y);
        acc.x = fmaf(e0, a01.x, acc.x); acc.y = fmaf(e0, a01.y, acc.y);
        acc.z = fmaf(e0, a23.x, acc.z); acc.w = fmaf(e0, a23.y, acc.w);
        a01 = __half22float2(*(const __half2*)&w1.x);
        a23 = __half22float2(*(const __half2*)&w1.y);
        acc.x = fmaf(e1, a01.x, acc.x); acc.y = fmaf(e1, a01.y, acc.y);
        acc.z = fmaf(e1, a23.x, acc.z); acc.w = fmaf(e1, a23.y, acc.w);
        a01 = __half22float2(*(const __half2*)&w2.x);
        a23 = __half22float2(*(const __half2*)&w2.y);
        acc.x = fmaf(e2, a01.x, acc.x); acc.y = fmaf(e2, a01.y, acc.y);
        acc.z = fmaf(e2, a23.x, acc.z); acc.w = fmaf(e2, a23.y, acc.w);
        a01 = __half22float2(*(const __half2*)&w3.x);
        a23 = __half22float2(*(const __half2*)&w3.y);
        acc.x = fmaf(e3, a01.x, acc.x); acc.y = fmaf(e3, a01.y, acc.y);
        acc.z = fmaf(e3, a23.x, acc.z); acc.w = fmaf(e3, a23.y, acc.w);
    }
    for (; i < r1; i++) {
        int src = g_col[i];
        float ex = __expf(leaky(g_as2[src] + adv));
        s += ex;
        uint2 raw = ((const uint2*)&g_h2[src * FF])[lane];
        float2 h01 = __half22float2(*(const __half2*)&raw.x);
        float2 h23 = __half22float2(*(const __half2*)&raw.y);
        acc.x = fmaf(ex, h01.x, acc.x);
        acc.y = fmaf(ex, h01.y, acc.y);
        acc.z = fmaf(ex, h23.x, acc.z);
        acc.w = fmaf(ex, h23.y, acc.w);
    }
    s = (s > 0.f) ? s : 1.f;
    float4 bv = ((const float4*)b2)[lane];
    float4 r;
    r.x = acc.x / s + bv.x;
    r.y = acc.y / s + bv.y;
    r.z = acc.z / s + bv.z;
    r.w = acc.w / s + bv.w;
    ((float4*)&out[w * FF])[lane] = r;
}

// ---------------- launcher (R9 structure; gemm1 at launch #4) -------------
extern "C" void kernel_launch(void* const* d_in, const int* in_sizes, int n_in,
                              void* d_out, int out_size) {
    const float* x   = (const float*)d_in[0];
    const void*  ei  = d_in[1];
    const float* W1  = (const float*)d_in[2];
    const float* as1 = (const float*)d_in[3];
    const float* ad1 = (const float*)d_in[4];
    const float* b1  = (const float*)d_in[5];
    const float* W2  = (const float*)d_in[6];
    const float* as2 = (const float*)d_in[7];
    const float* ad2 = (const float*)d_in[8];
    const float* b2  = (const float*)d_in[9];
    float*       out = (float*)d_out;

    int N    = in_sizes[0] / FF;     // 50000
    int E    = in_sizes[1] / 2;      // 800000
    int Etot = E + N;
    int nb   = (N + 255) / 256;      // 196 (<=256 required by k_scan2)

    k_zero_detect<<<nb, 256>>>((const int*)ei, N);
    k_hist<<<(Etot + 255) / 256, 256>>>(ei, E, Etot);
    k_bsum<<<nb, 256>>>(N);
    k_gemm1<<<(N + 127) / 128, 256>>>(x, W1, as1, ad1, N);   // launch #4 (profiled)
    k_scan2<<<nb, 256>>>(N, Etot);
    k_scatter<<<(Etot + 255) / 256, 256>>>(ei, E, Etot);

    k_agg1<<<(N * 32 + 255) / 256, 256>>>(b1, N);

    k_gemm2<<<(N + 63) / 64, 256>>>(W2, as2, ad2, N);
    k_agg2<<<(N * 32 + 255) / 256, 256>>>(out, b2, N);
}

// round 16
// speedup vs baseline: 1.1217x; 1.0096x over previous
#include <cuda_runtime.h>
#include <cuda_fp16.h>
#include <math.h>

// Fixed problem shape (per reference setup_inputs)
#define NN 50000
#define FF 128
#define H1 8
#define C1 8
#define HC1 64
#define EMAX 900000   // E (800000) + N (50000) self loops

// ---------------- device scratch (no allocation allowed) ----------------
__device__ __align__(16) __half g_h1[NN * HC1];   // layer1 features (fp16)
__device__ __align__(16) __half g_x2h[NN * HC1];  // ELU(layer1 out) fp16 (gathers)
__device__ __align__(16) float  g_aggv[NN * HC1]; // layer2 aggregated x2 (fp32)
__device__ float g_as1[NN * H1];
__device__ float g_ad1[NN * H1];
__device__ float g_as2[NN];
__device__ float g_ad2[NN];
__device__ float g_wts[HC1];                      // W2 @ att_s  (64)
__device__ float g_wtd[HC1];                      // W2 @ att_d  (64)
__device__ int   g_rowptr[NN + 1];
__device__ int   g_cnt[NN];
__device__ int   g_col[EMAX];                     // src ids grouped by dst
__device__ int   g_bsum[256];
__device__ int   g_is64;

// ---------------- helpers ----------------
__device__ __forceinline__ float leaky(float x) { return x > 0.0f ? x : 0.2f * x; }

__device__ __forceinline__ void fma2(unsigned long long& d, unsigned long long a,
                                     unsigned long long b, unsigned long long c) {
    asm("fma.rn.f32x2 %0, %1, %2, %3;" : "=l"(d) : "l"(a), "l"(b), "l"(c));
}
__device__ __forceinline__ unsigned long long dup2(float x) {
    unsigned long long d;
    unsigned int u = __float_as_uint(x);
    asm("mov.b64 %0, {%1, %2};" : "=l"(d) : "r"(u), "r"(u));
    return d;
}
__device__ __forceinline__ void unpack2(unsigned long long v, float& lo, float& hi) {
    unsigned int a, b;
    asm("mov.b64 {%0, %1}, %2;" : "=r"(a), "=r"(b) : "l"(v));
    lo = __uint_as_float(a);
    hi = __uint_as_float(b);
}

__device__ __forceinline__ void load_edge(const void* ei, int E, int e,
                                          int& src, int& dst) {
    if (g_is64) {
        const long long* p = (const long long*)ei;
        src = (int)p[e]; dst = (int)p[E + e];
    } else {
        const int* p = (const int*)ei;
        src = p[e]; dst = p[E + e];
    }
}
__device__ __forceinline__ int load_dst(const void* ei, int E, int e) {
    if (g_is64) return (int)((const long long*)ei)[E + e];
    return ((const int*)ei)[E + e];
}

// ------- zero counts + dtype probe + folded layer2 att vectors ------------
// w̃s[k] = sum_c W2[k,c]*att_s[c]; threads 0..63 of block 0 compute them.
__global__ void k_zero_detect(const int* __restrict__ ei32,
                              const float* __restrict__ W2,
                              const float* __restrict__ as2v,
                              const float* __restrict__ ad2v, int N) {
    int i = blockIdx.x * blockDim.x + threadIdx.x;
    if (i < N) g_cnt[i] = 0;
    if (blockIdx.x == 0) {
        if (threadIdx.x == 0) {
            int is64 = 1;
#pragma unroll
            for (int k = 0; k < 8; k++)
                if (ei32[2 * k + 1] != 0) is64 = 0;
            g_is64 = is64;
        }
        if (threadIdx.x < HC1) {
            int k = threadIdx.x;
            float s = 0.f, d = 0.f;
            const float4* wr = (const float4*)(W2 + k * FF);
#pragma unroll
            for (int c4 = 0; c4 < FF / 4; c4++) {
                float4 w = wr[c4];
                float4 a = ((const float4*)as2v)[c4];
                float4 b = ((const float4*)ad2v)[c4];
                s += w.x*a.x + w.y*a.y + w.z*a.z + w.w*a.w;
                d += w.x*b.x + w.y*b.y + w.z*b.z + w.w*b.w;
            }
            g_wts[k] = s;
            g_wtd[k] = d;
        }
    }
}

__global__ void k_hist(const void* __restrict__ ei, int E, int Etot) {
    int e = blockIdx.x * blockDim.x + threadIdx.x;
    if (e >= Etot) return;
    int dst = (e < E) ? load_dst(ei, E, e) : e - E;
    atomicAdd(&g_cnt[dst], 1);
}

__global__ void k_bsum(int N) {
    __shared__ int red[256];
    int i = blockIdx.x * 256 + threadIdx.x;
    red[threadIdx.x] = (i < N) ? g_cnt[i] : 0;
    __syncthreads();
#pragma unroll
    for (int off = 128; off > 0; off >>= 1) {
        if (threadIdx.x < off) red[threadIdx.x] += red[threadIdx.x + off];
        __syncthreads();
    }
    if (threadIdx.x == 0) g_bsum[blockIdx.x] = red[0];
}

__global__ void k_scan2(int N, int Etot) {
    __shared__ int s[256];
    __shared__ int wred[8];
    int t = threadIdx.x;
    int lane = t & 31, wid = t >> 5;

    int bv = (t < blockIdx.x) ? g_bsum[t] : 0;
#pragma unroll
    for (int off = 16; off > 0; off >>= 1)
        bv += __shfl_xor_sync(0xFFFFFFFF, bv, off);
    if (lane == 0) wred[wid] = bv;

    int i = blockIdx.x * 256 + t;
    int c = (i < N) ? g_cnt[i] : 0;
    s[t] = c;
    __syncthreads();
#pragma unroll
    for (int off = 1; off < 256; off <<= 1) {
        int u = (t >= off) ? s[t - off] : 0;
        __syncthreads();
        s[t] += u;
        __syncthreads();
    }
    int boff = wred[0] + wred[1] + wred[2] + wred[3]
             + wred[4] + wred[5] + wred[6] + wred[7];
    if (i < N) {
        g_rowptr[i] = s[t] - c + boff;
        g_cnt[i] = 0;
        if (i == N - 1) g_rowptr[N] = Etot;
    }
}

__global__ void k_scatter(const void* __restrict__ ei, int E, int Etot) {
    int e = blockIdx.x * blockDim.x + threadIdx.x;
    if (e >= Etot) return;
    int src, dst;
    if (e < E) load_edge(ei, E, e, src, dst);
    else       src = dst = e - E;
    int pos = g_rowptr[dst] + atomicAdd(&g_cnt[dst], 1);
    g_col[pos] = src;
}

// ---------------- layer1 GEMM + fused logits (R15, batched fills) ---------
__global__ void __launch_bounds__(256) k_gemm1(const float* __restrict__ x,
                                               const float* __restrict__ W1,
                                               const float* __restrict__ att_s,
                                               const float* __restrict__ att_d,
                                               int N) {
    __shared__ float ws[64 * HC1];       // 16KB [k][c], half-K
    __shared__ float xs[64 * 128];       // 32KB [k][n], half-K, 128 nodes
    int tid = threadIdx.x;
    int nbase = blockIdx.x * 128;
    int cg = tid & 15, ng = tid >> 4;
    int c0 = cg * 4, n0 = ng * 8;
    unsigned long long acc[8][2] = {};

    for (int half = 0; half < 2; half++) {
        float4 wtmp[4];
        {
            const float4* W4 = (const float4*)(W1 + half * 64 * HC1);
#pragma unroll
            for (int j = 0; j < 4; j++) wtmp[j] = W4[tid + j * 256];
        }
        float4 xtmp[8];
#pragma unroll
        for (int j = 0; j < 8; j++) {
            int i = tid + j * 256;
            int n = i & 127, k4 = i >> 7;
            int gn = nbase + n;
            xtmp[j] = (gn < N)
                ? ((const float4*)x)[(size_t)gn * 32 + half * 16 + k4]
                : make_float4(0.f, 0.f, 0.f, 0.f);
        }
        {
            float4* ws4 = (float4*)ws;
#pragma unroll
            for (int j = 0; j < 4; j++) ws4[tid + j * 256] = wtmp[j];
        }
#pragma unroll
        for (int j = 0; j < 8; j++) {
            int i = tid + j * 256;
            int n = i & 127, k4 = i >> 7;
            xs[(k4 * 4 + 0) * 128 + n] = xtmp[j].x;
            xs[(k4 * 4 + 1) * 128 + n] = xtmp[j].y;
            xs[(k4 * 4 + 2) * 128 + n] = xtmp[j].z;
            xs[(k4 * 4 + 3) * 128 + n] = xtmp[j].w;
        }
        __syncthreads();
#pragma unroll 16
        for (int k = 0; k < 64; k++) {
            ulonglong2 wv = ((const ulonglong2*)(ws + k * HC1))[cg];
            float4 xa = ((const float4*)(xs + k * 128))[ng * 2];
            float4 xb = ((const float4*)(xs + k * 128))[ng * 2 + 1];
            unsigned long long xd[8];
            xd[0] = dup2(xa.x); xd[1] = dup2(xa.y); xd[2] = dup2(xa.z); xd[3] = dup2(xa.w);
            xd[4] = dup2(xb.x); xd[5] = dup2(xb.y); xd[6] = dup2(xb.z); xd[7] = dup2(xb.w);
#pragma unroll
            for (int i = 0; i < 8; i++) {
                fma2(acc[i][0], xd[i], wv.x, acc[i][0]);
                fma2(acc[i][1], xd[i], wv.y, acc[i][1]);
            }
        }
        __syncthreads();
    }

    float sa0 = att_s[c0], sa1 = att_s[c0+1], sa2 = att_s[c0+2], sa3 = att_s[c0+3];
    float da0 = att_d[c0], da1 = att_d[c0+1], da2 = att_d[c0+2], da3 = att_d[c0+3];
    int head = cg >> 1;
#pragma unroll
    for (int i = 0; i < 8; i++) {
        float a0, a1, a2, a3;
        unpack2(acc[i][0], a0, a1);
        unpack2(acc[i][1], a2, a3);
        int gn = nbase + n0 + i;
        if (gn < N) {
            *((__half2*)&g_h1[gn * HC1 + c0])     = __floats2half2_rn(a0, a1);
            *((__half2*)&g_h1[gn * HC1 + c0 + 2]) = __floats2half2_rn(a2, a3);
        }
        float s = a0*sa0 + a1*sa1 + a2*sa2 + a3*sa3;
        float d = a0*da0 + a1*da1 + a2*da2 + a3*da3;
        s += __shfl_xor_sync(0xFFFFFFFF, s, 1);
        d += __shfl_xor_sync(0xFFFFFFFF, d, 1);
        if ((cg & 1) == 0 && gn < N) {
            g_as1[gn * H1 + head] = s;
            g_ad1[gn * H1 + head] = d;
        }
    }
}

// ------- layer1 aggregate + ELU + fused layer2 logits ---------------------
// warp per dst. After x2 is formed (fp32 in regs): store fp16 copy for the
// layer2 gathers AND compute as2/ad2 = x2 . w̃ via full-warp reduction.
__global__ void k_agg1(const float* __restrict__ b1, int N) {
    int w = (blockIdx.x * blockDim.x + threadIdx.x) >> 5;
    if (w >= N) return;
    int lane = threadIdx.x & 31;
    int head = lane >> 2, q = lane & 3;
    int r0 = g_rowptr[w], r1 = g_rowptr[w + 1];
    float adv = g_ad1[w * H1 + head];
    float s = 0.f, a0 = 0.f, a1 = 0.f;
    int i = r0;
    for (; i + 4 <= r1; i += 4) {
        int s0 = g_col[i], s1 = g_col[i+1], s2 = g_col[i+2], s3 = g_col[i+3];
        float l0 = g_as1[s0 * H1 + head];
        float l1 = g_as1[s1 * H1 + head];
        float l2 = g_as1[s2 * H1 + head];
        float l3 = g_as1[s3 * H1 + head];
        __half2 p0 = *(const __half2*)&g_h1[s0 * HC1 + head * C1 + q * 2];
        __half2 p1 = *(const __half2*)&g_h1[s1 * HC1 + head * C1 + q * 2];
        __half2 p2 = *(const __half2*)&g_h1[s2 * HC1 + head * C1 + q * 2];
        __half2 p3 = *(const __half2*)&g_h1[s3 * HC1 + head * C1 + q * 2];
        float e0 = __expf(leaky(l0 + adv));
        float e1 = __expf(leaky(l1 + adv));
        float e2 = __expf(leaky(l2 + adv));
        float e3 = __expf(leaky(l3 + adv));
        s += (e0 + e1) + (e2 + e3);
        float2 h0 = __half22float2(p0), h1v = __half22float2(p1);
        float2 h2v = __half22float2(p2), h3 = __half22float2(p3);
        a0 = fmaf(e0, h0.x, a0);  a1 = fmaf(e0, h0.y, a1);
        a0 = fmaf(e1, h1v.x, a0); a1 = fmaf(e1, h1v.y, a1);
        a0 = fmaf(e2, h2v.x, a0); a1 = fmaf(e2, h2v.y, a1);
        a0 = fmaf(e3, h3.x, a0);  a1 = fmaf(e3, h3.y, a1);
    }
    for (; i < r1; i++) {
        int src = g_col[i];
        float ex = __expf(leaky(g_as1[src * H1 + head] + adv));
        s += ex;
        float2 hv = __half22float2(*(const __half2*)&g_h1[src * HC1 + head * C1 + q * 2]);
        a0 = fmaf(ex, hv.x, a0);
        a1 = fmaf(ex, hv.y, a1);
    }
    s = (s > 0.f) ? s : 1.f;
    int j = head * C1 + q * 2;
    float v0 = a0 / s + b1[j];
    float v1 = a1 / s + b1[j + 1];
    v0 = v0 > 0.f ? v0 : expm1f(v0);
    v1 = v1 > 0.f ? v1 : expm1f(v1);
    // fp16 copy for layer2 gathers (each lane owns channels j, j+1)
    *(__half2*)&g_x2h[w * HC1 + j] = __floats2half2_rn(v0, v1);
    // fused layer2 logits: warp covers all 64 channels exactly once
    float ps = v0 * g_wts[j] + v1 * g_wts[j + 1];
    float pd = v0 * g_wtd[j] + v1 * g_wtd[j + 1];
#pragma unroll
    for (int off = 16; off > 0; off >>= 1) {
        ps += __shfl_xor_sync(0xFFFFFFFF, ps, off);
        pd += __shfl_xor_sync(0xFFFFFFFF, pd, off);
    }
    if (lane == 0) {
        g_as2[w] = ps;
        g_ad2[w] = pd;
    }
}

// ------- layer2 aggregate over 64-dim x2 (fp16 gathers, 128B/edge) --------
// warp per dst; lane handles channels lane*2, lane*2+1.
__global__ void k_agg2(int N) {
    int w = (blockIdx.x * blockDim.x + threadIdx.x) >> 5;
    if (w >= N) return;
    int lane = threadIdx.x & 31;
    int r0 = g_rowptr[w], r1 = g_rowptr[w + 1];
    float adv = g_ad2[w];
    float s = 0.f, a0 = 0.f, a1 = 0.f;
    int i = r0;
    for (; i + 4 <= r1; i += 4) {
        int s0 = g_col[i], s1 = g_col[i+1], s2 = g_col[i+2], s3 = g_col[i+3];
        float l0 = g_as2[s0], l1 = g_as2[s1], l2 = g_as2[s2], l3 = g_as2[s3];
        __half2 p0 = ((const __half2*)&g_x2h[s0 * HC1])[lane];
        __half2 p1 = ((const __half2*)&g_x2h[s1 * HC1])[lane];
        __half2 p2 = ((const __half2*)&g_x2h[s2 * HC1])[lane];
        __half2 p3 = ((const __half2*)&g_x2h[s3 * HC1])[lane];
        float e0 = __expf(leaky(l0 + adv));
        float e1 = __expf(leaky(l1 + adv));
        float e2 = __expf(leaky(l2 + adv));
        float e3 = __expf(leaky(l3 + adv));
        s += (e0 + e1) + (e2 + e3);
        float2 h0 = __half22float2(p0), h1 = __half22float2(p1);
        float2 h2 = __half22float2(p2), h3 = __half22float2(p3);
        a0 = fmaf(e0, h0.x, a0); a1 = fmaf(e0, h0.y, a1);
        a0 = fmaf(e1, h1.x, a0); a1 = fmaf(e1, h1.y, a1);
        a0 = fmaf(e2, h2.x, a0); a1 = fmaf(e2, h2.y, a1);
        a0 = fmaf(e3, h3.x, a0); a1 = fmaf(e3, h3.y, a1);
    }
    for (; i < r1; i++) {
        int src = g_col[i];
        float ex = __expf(leaky(g_as2[src] + adv));
        s += ex;
        float2 hv = __half22float2(((const __half2*)&g_x2h[src * HC1])[lane]);
        a0 = fmaf(ex, hv.x, a0);
        a1 = fmaf(ex, hv.y, a1);
    }
    s = (s > 0.f) ? s : 1.f;
    float2 r;
    r.x = a0 / s;
    r.y = a1 / s;
    *(float2*)&g_aggv[w * HC1 + lane * 2] = r;
}

// ------- final GEMM: out = aggv @ W2 + b2 (64 nodes/block, staged fills) --
__global__ void __launch_bounds__(256) k_gemm_out(const float* __restrict__ W2,
                                                  const float* __restrict__ b2,
                                                  float* __restrict__ out, int N) {
    __shared__ float ws[HC1 * FF];       // 32KB [k][c]
    __shared__ float xs[HC1 * 64];       // 16KB [k][n] transposed
    int tid = threadIdx.x;
    int nbase = blockIdx.x * 64;

    float4 wtmp[8];
    {
        const float4* W4 = (const float4*)W2;
#pragma unroll
        for (int j = 0; j < 8; j++) wtmp[j] = W4[tid + j * 256];
    }
    float4 xtmp[4];
#pragma unroll
    for (int j = 0; j < 4; j++) {
        int i = tid + j * 256;
        int n = i & 63, k4 = i >> 6;
        int gn = nbase + n;
        xtmp[j] = (gn < N) ? ((const float4*)g_aggv)[(size_t)gn * 16 + k4]
                           : make_float4(0.f, 0.f, 0.f, 0.f);
    }
    {
        float4* ws4 = (float4*)ws;
#pragma unroll
        for (int j = 0; j < 8; j++) ws4[tid + j * 256] = wtmp[j];
    }
#pragma unroll
    for (int j = 0; j < 4; j++) {
        int i = tid + j * 256;
        int n = i & 63, k4 = i >> 6;
        xs[(k4 * 4 + 0) * 64 + n] = xtmp[j].x;
        xs[(k4 * 4 + 1) * 64 + n] = xtmp[j].y;
        xs[(k4 * 4 + 2) * 64 + n] = xtmp[j].z;
        xs[(k4 * 4 + 3) * 64 + n] = xtmp[j].w;
    }
    __syncthreads();
    int cg = tid & 31, ng = tid >> 5;
    int c0 = cg * 4, n0 = ng * 8;
    unsigned long long acc[8][2] = {};
#pragma unroll 16
    for (int k = 0; k < HC1; k++) {
        ulonglong2 wv = ((const ulonglong2*)(ws + k * FF))[cg];
        float4 xa = ((const float4*)(xs + k * 64))[ng * 2];
        float4 xb = ((const float4*)(xs + k * 64))[ng * 2 + 1];
        unsigned long long xd[8];
        xd[0] = dup2(xa.x); xd[1] = dup2(xa.y); xd[2] = dup2(xa.z); xd[3] = dup2(xa.w);
        xd[4] = dup2(xb.x); xd[5] = dup2(xb.y); xd[6] = dup2(xb.z); xd[7] = dup2(xb.w);
#pragma unroll
        for (int i = 0; i < 8; i++) {
            fma2(acc[i][0], xd[i], wv.x, acc[i][0]);
            fma2(acc[i][1], xd[i], wv.y, acc[i][1]);
        }
    }
    float4 bv = ((const float4*)b2)[cg];
#pragma unroll
    for (int i = 0; i < 8; i++) {
        float a0, a1, a2, a3;
        unpack2(acc[i][0], a0, a1);
        unpack2(acc[i][1], a2, a3);
        int gn = nbase + n0 + i;
        if (gn < N) {
            float4 r = make_float4(a0 + bv.x, a1 + bv.y, a2 + bv.z, a3 + bv.w);
            ((float4*)&out[gn * FF])[cg] = r;
        }
    }
}

// ---------------- launcher (gemm1 at launch #4 for profiling) -------------
extern "C" void kernel_launch(void* const* d_in, const int* in_sizes, int n_in,
                              void* d_out, int out_size) {
    const float* x   = (const float*)d_in[0];
    const void*  ei  = d_in[1];
    const float* W1  = (const float*)d_in[2];
    const float* as1 = (const float*)d_in[3];
    const float* ad1 = (const float*)d_in[4];
    const float* b1  = (const float*)d_in[5];
    const float* W2  = (const float*)d_in[6];
    const float* as2 = (const float*)d_in[7];
    const float* ad2 = (const float*)d_in[8];
    const float* b2  = (const float*)d_in[9];
    float*       out = (float*)d_out;

    int N    = in_sizes[0] / FF;     // 50000
    int E    = in_sizes[1] / 2;      // 800000
    int Etot = E + N;
    int nb   = (N + 255) / 256;      // 196 (<=256 required by k_scan2)

    k_zero_detect<<<nb, 256>>>((const int*)ei, W2, as2, ad2, N);
    k_hist<<<(Etot + 255) / 256, 256>>>(ei, E, Etot);
    k_bsum<<<nb, 256>>>(N);
    k_gemm1<<<(N + 127) / 128, 256>>>(x, W1, as1, ad1, N);   // launch #4 (profiled)
    k_scan2<<<nb, 256>>>(N, Etot);
    k_scatter<<<(Etot + 255) / 256, 256>>>(ei, E, Etot);

    k_agg1<<<(N * 32 + 255) / 256, 256>>>(b1, N);
    k_agg2<<<(N * 32 + 255) / 256, 256>>>(N);
    k_gemm_out<<<(N + 63) / 64, 256>>>(W2, b2, out, N);
}